// round 3
// baseline (speedup 1.0000x reference)
#include <cuda_runtime.h>
#include <math.h>
#include <math_constants.h>

// Problem constants
#define B_ 4
#define S_ 2048
#define D_ 1024
#define M_ (B_*S_)   // 8192

// Scratch (allocation-free: __device__ globals)
__device__ float g_q[M_*D_];
__device__ float g_k[M_*D_];
__device__ float g_v[M_*D_];
__device__ float g_s[(size_t)B_*S_*S_];   // scores / probabilities, 64 MB

// Tiling
#define BM 128
#define BN 128
#define BK 16
#define TM 8
#define TN 8
#define PADW (BM + 4)   // smem row padding to avoid STS bank conflicts
#define NTHR 256

// ---------------------------------------------------------------------------
// NT GEMM: C[M,N] = A[M,K] * B[N,K]^T   (both K-contiguous, row-major)
// Used for QKV projections.
// ---------------------------------------------------------------------------
__global__ __launch_bounds__(NTHR)
void gemm_nt_kernel(const float* __restrict__ A, const float* __restrict__ Bm,
                    float* __restrict__ C, int M, int N, int K)
{
    __shared__ float As[BK][PADW];
    __shared__ float Bs[BK][PADW];

    const int bx = blockIdx.x;            // N tile
    const int by = blockIdx.y;            // M tile
    const int tid = threadIdx.x;
    const int tx = tid & 15;
    const int ty = tid >> 4;

    const float* Ablk = A + (size_t)by * BM * K;
    const float* Bblk = Bm + (size_t)bx * BN * K;

    float acc[TM][TN];
    #pragma unroll
    for (int i = 0; i < TM; ++i)
        #pragma unroll
        for (int j = 0; j < TN; ++j) acc[i][j] = 0.f;

    for (int k0 = 0; k0 < K; k0 += BK) {
        // Load A tile: 128 rows x 16 k, transposed into As[k][row]
        #pragma unroll
        for (int it = 0; it < 2; ++it) {
            int f = tid + it * NTHR;
            int row = f >> 2;
            int kc  = (f & 3) << 2;
            float4 v = *reinterpret_cast<const float4*>(Ablk + (size_t)row * K + k0 + kc);
            As[kc+0][row] = v.x; As[kc+1][row] = v.y;
            As[kc+2][row] = v.z; As[kc+3][row] = v.w;
        }
        #pragma unroll
        for (int it = 0; it < 2; ++it) {
            int f = tid + it * NTHR;
            int row = f >> 2;
            int kc  = (f & 3) << 2;
            float4 v = *reinterpret_cast<const float4*>(Bblk + (size_t)row * K + k0 + kc);
            Bs[kc+0][row] = v.x; Bs[kc+1][row] = v.y;
            Bs[kc+2][row] = v.z; Bs[kc+3][row] = v.w;
        }
        __syncthreads();

        #pragma unroll
        for (int k = 0; k < BK; ++k) {
            float4 a0 = *reinterpret_cast<const float4*>(&As[k][ty*TM]);
            float4 a1 = *reinterpret_cast<const float4*>(&As[k][ty*TM+4]);
            float4 b0 = *reinterpret_cast<const float4*>(&Bs[k][tx*TN]);
            float4 b1 = *reinterpret_cast<const float4*>(&Bs[k][tx*TN+4]);
            float a[TM] = {a0.x,a0.y,a0.z,a0.w,a1.x,a1.y,a1.z,a1.w};
            float b[TN] = {b0.x,b0.y,b0.z,b0.w,b1.x,b1.y,b1.z,b1.w};
            #pragma unroll
            for (int i = 0; i < TM; ++i)
                #pragma unroll
                for (int j = 0; j < TN; ++j)
                    acc[i][j] = fmaf(a[i], b[j], acc[i][j]);
        }
        __syncthreads();
    }

    #pragma unroll
    for (int i = 0; i < TM; ++i) {
        float* Crow = C + (size_t)(by*BM + ty*TM + i) * N + bx*BN + tx*TN;
        *reinterpret_cast<float4*>(Crow)   = make_float4(acc[i][0],acc[i][1],acc[i][2],acc[i][3]);
        *reinterpret_cast<float4*>(Crow+4) = make_float4(acc[i][4],acc[i][5],acc[i][6],acc[i][7]);
    }
}

// ---------------------------------------------------------------------------
// Scores: S[b,q,k] = (Q[b,q,:] . K[b,k,:]) / sqrt(D), causal masked.
// Blocks with bn > bm are fully masked -> skipped entirely (never read later).
// ---------------------------------------------------------------------------
__global__ __launch_bounds__(NTHR)
void scores_kernel()
{
    const int bx = blockIdx.x;    // key tile
    const int by = blockIdx.y;    // query tile
    if (bx > by) return;          // fully above diagonal
    const int b  = blockIdx.z;

    __shared__ float As[BK][PADW];
    __shared__ float Bs[BK][PADW];

    const int tid = threadIdx.x;
    const int tx = tid & 15;
    const int ty = tid >> 4;

    const float* Ablk = g_q + (size_t)b * S_ * D_ + (size_t)by * BM * D_;
    const float* Bblk = g_k + (size_t)b * S_ * D_ + (size_t)bx * BN * D_;
    float* C = g_s + (size_t)b * S_ * S_;

    float acc[TM][TN];
    #pragma unroll
    for (int i = 0; i < TM; ++i)
        #pragma unroll
        for (int j = 0; j < TN; ++j) acc[i][j] = 0.f;

    for (int k0 = 0; k0 < D_; k0 += BK) {
        #pragma unroll
        for (int it = 0; it < 2; ++it) {
            int f = tid + it * NTHR;
            int row = f >> 2;
            int kc  = (f & 3) << 2;
            float4 v = *reinterpret_cast<const float4*>(Ablk + (size_t)row * D_ + k0 + kc);
            As[kc+0][row] = v.x; As[kc+1][row] = v.y;
            As[kc+2][row] = v.z; As[kc+3][row] = v.w;
        }
        #pragma unroll
        for (int it = 0; it < 2; ++it) {
            int f = tid + it * NTHR;
            int row = f >> 2;
            int kc  = (f & 3) << 2;
            float4 v = *reinterpret_cast<const float4*>(Bblk + (size_t)row * D_ + k0 + kc);
            Bs[kc+0][row] = v.x; Bs[kc+1][row] = v.y;
            Bs[kc+2][row] = v.z; Bs[kc+3][row] = v.w;
        }
        __syncthreads();

        #pragma unroll
        for (int k = 0; k < BK; ++k) {
            float4 a0 = *reinterpret_cast<const float4*>(&As[k][ty*TM]);
            float4 a1 = *reinterpret_cast<const float4*>(&As[k][ty*TM+4]);
            float4 b0 = *reinterpret_cast<const float4*>(&Bs[k][tx*TN]);
            float4 b1 = *reinterpret_cast<const float4*>(&Bs[k][tx*TN+4]);
            float a[TM] = {a0.x,a0.y,a0.z,a0.w,a1.x,a1.y,a1.z,a1.w};
            float bb[TN] = {b0.x,b0.y,b0.z,b0.w,b1.x,b1.y,b1.z,b1.w};
            #pragma unroll
            for (int i = 0; i < TM; ++i)
                #pragma unroll
                for (int j = 0; j < TN; ++j)
                    acc[i][j] = fmaf(a[i], bb[j], acc[i][j]);
        }
        __syncthreads();
    }

    const float alpha = 0.03125f;   // 1/sqrt(1024)
    const bool diag = (bx == by);
    #pragma unroll
    for (int i = 0; i < TM; ++i) {
        int row = by*BM + ty*TM + i;
        float* Crow = C + (size_t)row * S_ + bx*BN + tx*TN;
        float vals[TN];
        #pragma unroll
        for (int j = 0; j < TN; ++j) {
            int col = bx*BN + tx*TN + j;
            float vv = acc[i][j] * alpha;
            if (diag && col > row) vv = -CUDART_INF_F;
            vals[j] = vv;
        }
        *reinterpret_cast<float4*>(Crow)   = make_float4(vals[0],vals[1],vals[2],vals[3]);
        *reinterpret_cast<float4*>(Crow+4) = make_float4(vals[4],vals[5],vals[6],vals[7]);
    }
}

// ---------------------------------------------------------------------------
// Row softmax over causal prefix. Row q reads [0, L) where L = next 128-mult.
// exp(-inf) = 0 handles the diagonal-block masked tail; writes probs in place.
// ---------------------------------------------------------------------------
__global__ __launch_bounds__(NTHR)
void softmax_kernel()
{
    const int q = blockIdx.x;
    const int b = blockIdx.y;
    float* row = g_s + (size_t)b * S_ * S_ + (size_t)q * S_;
    const int L = ((q >> 7) + 1) << 7;

    __shared__ float red[NTHR];
    const int tid = threadIdx.x;

    float m = -CUDART_INF_F;
    for (int i = tid; i < L; i += NTHR) m = fmaxf(m, row[i]);
    red[tid] = m; __syncthreads();
    for (int s = NTHR/2; s > 0; s >>= 1) {
        if (tid < s) red[tid] = fmaxf(red[tid], red[tid+s]);
        __syncthreads();
    }
    m = red[0]; __syncthreads();

    float sum = 0.f;
    for (int i = tid; i < L; i += NTHR) {
        float e = __expf(row[i] - m);
        row[i] = e;
        sum += e;
    }
    red[tid] = sum; __syncthreads();
    for (int s = NTHR/2; s > 0; s >>= 1) {
        if (tid < s) red[tid] += red[tid+s];
        __syncthreads();
    }
    float inv = 1.0f / red[0];
    for (int i = tid; i < L; i += NTHR) row[i] *= inv;
}

// ---------------------------------------------------------------------------
// Out = P @ V (NN GEMM). Per query row-block, k loop truncated at the causal
// boundary kmax = (by+1)*128.
// ---------------------------------------------------------------------------
__global__ __launch_bounds__(NTHR)
void pv_kernel(float* __restrict__ out)
{
    const int bx = blockIdx.x;   // output d tile
    const int by = blockIdx.y;   // query tile
    const int b  = blockIdx.z;

    __shared__ float As[BK][PADW];
    __shared__ float Bs[BK][PADW];

    const int tid = threadIdx.x;
    const int tx = tid & 15;
    const int ty = tid >> 4;

    const float* P = g_s + (size_t)b * S_ * S_ + (size_t)by * BM * S_;
    const float* V = g_v + (size_t)b * S_ * D_;
    const int kmax = (by + 1) * BM;

    float acc[TM][TN];
    #pragma unroll
    for (int i = 0; i < TM; ++i)
        #pragma unroll
        for (int j = 0; j < TN; ++j) acc[i][j] = 0.f;

    for (int k0 = 0; k0 < kmax; k0 += BK) {
        // A tile: P rows (K-contig) -> transposed As[k][m]
        #pragma unroll
        for (int it = 0; it < 2; ++it) {
            int f = tid + it * NTHR;
            int row = f >> 2;
            int kc  = (f & 3) << 2;
            float4 v = *reinterpret_cast<const float4*>(P + (size_t)row * S_ + k0 + kc);
            As[kc+0][row] = v.x; As[kc+1][row] = v.y;
            As[kc+2][row] = v.z; As[kc+3][row] = v.w;
        }
        // B tile: V[k0+k][n] contiguous along n -> Bs[k][n]
        #pragma unroll
        for (int it = 0; it < 2; ++it) {
            int f = tid + it * NTHR;
            int krow = f >> 5;
            int ncol = (f & 31) << 2;
            float4 v = *reinterpret_cast<const float4*>(V + (size_t)(k0 + krow) * D_ + bx*BN + ncol);
            *reinterpret_cast<float4*>(&Bs[krow][ncol]) = v;
        }
        __syncthreads();

        #pragma unroll
        for (int k = 0; k < BK; ++k) {
            float4 a0 = *reinterpret_cast<const float4*>(&As[k][ty*TM]);
            float4 a1 = *reinterpret_cast<const float4*>(&As[k][ty*TM+4]);
            float4 b0 = *reinterpret_cast<const float4*>(&Bs[k][tx*TN]);
            float4 b1 = *reinterpret_cast<const float4*>(&Bs[k][tx*TN+4]);
            float a[TM] = {a0.x,a0.y,a0.z,a0.w,a1.x,a1.y,a1.z,a1.w};
            float bb[TN] = {b0.x,b0.y,b0.z,b0.w,b1.x,b1.y,b1.z,b1.w};
            #pragma unroll
            for (int i = 0; i < TM; ++i)
                #pragma unroll
                for (int j = 0; j < TN; ++j)
                    acc[i][j] = fmaf(a[i], bb[j], acc[i][j]);
        }
        __syncthreads();
    }

    #pragma unroll
    for (int i = 0; i < TM; ++i) {
        float* Crow = out + (size_t)b * S_ * D_ + (size_t)(by*BM + ty*TM + i) * D_ + bx*BN + tx*TN;
        *reinterpret_cast<float4*>(Crow)   = make_float4(acc[i][0],acc[i][1],acc[i][2],acc[i][3]);
        *reinterpret_cast<float4*>(Crow+4) = make_float4(acc[i][4],acc[i][5],acc[i][6],acc[i][7]);
    }
}

// ---------------------------------------------------------------------------
extern "C" void kernel_launch(void* const* d_in, const int* in_sizes, int n_in,
                              void* d_out, int out_size)
{
    const float* x  = (const float*)d_in[0];
    const float* wq = (const float*)d_in[1];
    const float* wk = (const float*)d_in[2];
    const float* wv = (const float*)d_in[3];
    float* out = (float*)d_out;

    float *qp, *kp, *vp;
    cudaGetSymbolAddress((void**)&qp, g_q);
    cudaGetSymbolAddress((void**)&kp, g_k);
    cudaGetSymbolAddress((void**)&vp, g_v);

    dim3 blk(NTHR);

    // QKV projections: C[8192,1024] = X[8192,1024] * W[1024,1024]^T
    dim3 gproj(D_/BN, M_/BM);
    gemm_nt_kernel<<<gproj, blk>>>(x, wq, qp, M_, D_, D_);
    gemm_nt_kernel<<<gproj, blk>>>(x, wk, kp, M_, D_, D_);
    gemm_nt_kernel<<<gproj, blk>>>(x, wv, vp, M_, D_, D_);

    // Scores with causal mask (upper-triangular blocks skipped)
    dim3 gsc(S_/BN, S_/BM, B_);
    scores_kernel<<<gsc, blk>>>();

    // Softmax over causal prefix
    dim3 gsm(S_, B_);
    softmax_kernel<<<gsm, blk>>>();

    // Out = P @ V
    dim3 gpv(D_/BN, S_/BM, B_);
    pv_kernel<<<gpv, blk>>>(out);
}

// round 5
// speedup vs baseline: 2.5399x; 2.5399x over previous
#include <cuda_runtime.h>
#include <cuda_bf16.h>
#include <cstdint>
#include <math.h>
#include <math_constants.h>

#define B_ 4
#define S_ 2048
#define D_ 1024
#define M_ (B_*S_)   // 8192

typedef __nv_bfloat16 bf16;

// ---------------------------------------------------------------------------
// Scratch (__device__ globals; allocation-free)
// ---------------------------------------------------------------------------
__device__ __align__(256) bf16 g_xh[M_*D_], g_xl[M_*D_];
__device__ __align__(256) bf16 g_wqh[D_*D_], g_wql[D_*D_];
__device__ __align__(256) bf16 g_wkh[D_*D_], g_wkl[D_*D_];
__device__ __align__(256) bf16 g_wvh[D_*D_], g_wvl[D_*D_];
__device__ __align__(256) bf16 g_qh[M_*D_], g_ql[M_*D_];
__device__ __align__(256) bf16 g_kh[M_*D_], g_kl[M_*D_];
__device__ __align__(256) bf16 g_vh[M_*D_], g_vl[M_*D_];      // V natural [b][s][d]
__device__ __align__(256) float g_s[(size_t)B_*S_*S_];
__device__ __align__(256) bf16 g_ph[(size_t)B_*S_*S_], g_pl[(size_t)B_*S_*S_];

// ---------------------------------------------------------------------------
// Smem layout (dynamic). 2 stages. A tiles: 128 rows x 40 halves (pad).
// B NT tiles: 128 x 40 halves. B trans tiles (PV): 32 x 136 halves (8704B).
// All regions sized 10240B.
// ---------------------------------------------------------------------------
#define LDA_S 40
#define LDBT_S 136
#define OFF_AH(s) ((s)*10240u)
#define OFF_AL(s) (20480u + (s)*10240u)
#define OFF_BH(s) (40960u + (s)*10240u)
#define OFF_BL(s) (61440u + (s)*10240u)
#define SMEM_TOTAL 81920
#define NTHR 256

__device__ __forceinline__ uint32_t smem_u32(const void* p) {
    uint32_t a;
    asm("{ .reg .u64 t; cvta.to.shared.u64 t, %1; cvt.u32.u64 %0, t; }" : "=r"(a) : "l"(p));
    return a;
}
__device__ __forceinline__ void cpa16(uint32_t s, const void* g) {
    asm volatile("cp.async.cg.shared.global [%0], [%1], 16;" :: "r"(s), "l"(g));
}
__device__ __forceinline__ void ldm_x4(uint32_t addr, uint32_t r[4]) {
    asm volatile("ldmatrix.sync.aligned.m8n8.x4.shared.b16 {%0,%1,%2,%3}, [%4];"
        : "=r"(r[0]), "=r"(r[1]), "=r"(r[2]), "=r"(r[3]) : "r"(addr));
}
__device__ __forceinline__ void ldm_x4_t(uint32_t addr, uint32_t r[4]) {
    asm volatile("ldmatrix.sync.aligned.m8n8.x4.trans.shared.b16 {%0,%1,%2,%3}, [%4];"
        : "=r"(r[0]), "=r"(r[1]), "=r"(r[2]), "=r"(r[3]) : "r"(addr));
}
__device__ __forceinline__ void mma16816(float c[4], const uint32_t a[4], const uint32_t b[2]) {
    asm volatile("mma.sync.aligned.m16n8k16.row.col.f32.bf16.bf16.f32 "
        "{%0,%1,%2,%3}, {%4,%5,%6,%7}, {%8,%9}, {%0,%1,%2,%3};"
        : "+f"(c[0]), "+f"(c[1]), "+f"(c[2]), "+f"(c[3])
        : "r"(a[0]), "r"(a[1]), "r"(a[2]), "r"(a[3]), "r"(b[0]), "r"(b[1]));
}

// ---------------------------------------------------------------------------
// Stage load via cp.async. BT=0: B is [n][k] K-contig (NT). BT=1: B is [k][n]
// row-major (V natural layout), loaded untransposed into [32][136] tile.
// ---------------------------------------------------------------------------
template<int BT>
__device__ __forceinline__ void load_stage(uint32_t sb, int st, int tid,
    const bf16* __restrict__ Ah, const bf16* __restrict__ Al, int lda,
    const bf16* __restrict__ Bh, const bf16* __restrict__ Bl, int ldb, int k0)
{
    #pragma unroll
    for (int it = 0; it < 2; ++it) {
        int c = tid + it * NTHR;          // [0,512)
        int row = c >> 2;
        int kc  = (c & 3) << 3;           // halves
        uint32_t so = (uint32_t)((row * LDA_S + kc) * 2);
        cpa16(sb + OFF_AH(st) + so, Ah + (size_t)row * lda + k0 + kc);
        cpa16(sb + OFF_AL(st) + so, Al + (size_t)row * lda + k0 + kc);
        if (BT == 0) {
            cpa16(sb + OFF_BH(st) + so, Bh + (size_t)row * ldb + k0 + kc);
            cpa16(sb + OFF_BL(st) + so, Bl + (size_t)row * ldb + k0 + kc);
        } else {
            int br = c >> 4;              // k row [0,32)
            int bn = (c & 15) << 3;       // n halves [0,128)
            uint32_t bo = (uint32_t)((br * LDBT_S + bn) * 2);
            cpa16(sb + OFF_BH(st) + bo, Bh + (size_t)(k0 + br) * ldb + bn);
            cpa16(sb + OFF_BL(st) + bo, Bl + (size_t)(k0 + br) * ldb + bn);
        }
    }
}

// ---------------------------------------------------------------------------
// Compute one BK=32 stage: 2 k16-steps x (4x4 frags) x 3 split-MMAs.
// ---------------------------------------------------------------------------
template<int BT>
__device__ __forceinline__ void compute_stage(uint32_t sb, int st, int lane,
                                              int wm, int wn, float acc[4][4][4])
{
    const uint32_t sAh = sb + OFF_AH(st);
    const uint32_t sAl = sb + OFF_AL(st);
    const uint32_t sBh = sb + OFF_BH(st);
    const uint32_t sBl = sb + OFF_BL(st);

    #pragma unroll
    for (int ks = 0; ks < 2; ++ks) {
        uint32_t ah[4][4], al[4][4];
        {
            int arow = wm * 64 + (lane & 15);
            int akh  = ks * 16 + (lane >> 4) * 8;
            #pragma unroll
            for (int mi = 0; mi < 4; ++mi) {
                uint32_t off = (uint32_t)(((arow + mi * 16) * LDA_S + akh) * 2);
                ldm_x4(sAh + off, ah[mi]);
                ldm_x4(sAl + off, al[mi]);
            }
        }
        uint32_t bh[4][2], bl[4][2];
        if (BT == 0) {
            int nr = (lane & 7) + ((lane >> 4) & 1) * 8;
            int kh = ks * 16 + ((lane >> 3) & 1) * 8;
            #pragma unroll
            for (int np = 0; np < 2; ++np) {
                uint32_t off = (uint32_t)(((wn * 32 + np * 16 + nr) * LDA_S + kh) * 2);
                uint32_t r[4];
                ldm_x4(sBh + off, r);
                bh[2*np][0] = r[0]; bh[2*np][1] = r[1];
                bh[2*np+1][0] = r[2]; bh[2*np+1][1] = r[3];
                ldm_x4(sBl + off, r);
                bl[2*np][0] = r[0]; bl[2*np][1] = r[1];
                bl[2*np+1][0] = r[2]; bl[2*np+1][1] = r[3];
            }
        } else {
            int kr = ks * 16 + ((lane >> 3) & 1) * 8 + (lane & 7);
            int nh = ((lane >> 4) & 1) * 8;
            #pragma unroll
            for (int np = 0; np < 2; ++np) {
                uint32_t off = (uint32_t)((kr * LDBT_S + wn * 32 + np * 16 + nh) * 2);
                uint32_t r[4];
                ldm_x4_t(sBh + off, r);
                bh[2*np][0] = r[0]; bh[2*np][1] = r[1];
                bh[2*np+1][0] = r[2]; bh[2*np+1][1] = r[3];
                ldm_x4_t(sBl + off, r);
                bl[2*np][0] = r[0]; bl[2*np][1] = r[1];
                bl[2*np+1][0] = r[2]; bl[2*np+1][1] = r[3];
            }
        }
        #pragma unroll
        for (int mi = 0; mi < 4; ++mi)
            #pragma unroll
            for (int ni = 0; ni < 4; ++ni) {
                mma16816(acc[mi][ni], ah[mi], bh[ni]);
                mma16816(acc[mi][ni], ah[mi], bl[ni]);
                mma16816(acc[mi][ni], al[mi], bh[ni]);
            }
    }
}

// ---------------------------------------------------------------------------
// Full pipelined GEMM mainloop into register acc.
// ---------------------------------------------------------------------------
template<int BT>
__device__ __forceinline__ void gemm_run(uint32_t sb,
    const bf16* __restrict__ Ah, const bf16* __restrict__ Al, int lda,
    const bf16* __restrict__ Bh, const bf16* __restrict__ Bl, int ldb,
    int niter, float acc[4][4][4])
{
    const int tid = threadIdx.x;
    const int lane = tid & 31, wid = tid >> 5;
    const int wm = wid & 1, wn = wid >> 1;

    #pragma unroll
    for (int mi = 0; mi < 4; ++mi)
        #pragma unroll
        for (int ni = 0; ni < 4; ++ni)
            #pragma unroll
            for (int j = 0; j < 4; ++j) acc[mi][ni][j] = 0.f;

    load_stage<BT>(sb, 0, tid, Ah, Al, lda, Bh, Bl, ldb, 0);
    asm volatile("cp.async.commit_group;" ::: "memory");

    for (int i = 0; i < niter; ++i) {
        if (i + 1 < niter) {
            load_stage<BT>(sb, (i + 1) & 1, tid, Ah, Al, lda, Bh, Bl, ldb, (i + 1) * 32);
            asm volatile("cp.async.commit_group;" ::: "memory");
            asm volatile("cp.async.wait_group 1;" ::: "memory");
        } else {
            asm volatile("cp.async.wait_group 0;" ::: "memory");
        }
        __syncthreads();
        compute_stage<BT>(sb, i & 1, lane, wm, wn, acc);
        __syncthreads();
    }
}

// ---------------------------------------------------------------------------
// Split: fp32 -> bf16 hi/lo
// ---------------------------------------------------------------------------
__global__ __launch_bounds__(256)
void split_kernel(const float4* __restrict__ in, __nv_bfloat162* __restrict__ hi,
                  __nv_bfloat162* __restrict__ lo, int n4)
{
    int i = blockIdx.x * 256 + threadIdx.x;
    if (i >= n4) return;
    float4 x = in[i];
    bf16 h0 = __float2bfloat16(x.x); bf16 l0 = __float2bfloat16(x.x - __bfloat162float(h0));
    bf16 h1 = __float2bfloat16(x.y); bf16 l1 = __float2bfloat16(x.y - __bfloat162float(h1));
    bf16 h2 = __float2bfloat16(x.z); bf16 l2 = __float2bfloat16(x.z - __bfloat162float(h2));
    bf16 h3 = __float2bfloat16(x.w); bf16 l3 = __float2bfloat16(x.w - __bfloat162float(h3));
    hi[2*i]   = __halves2bfloat162(h0, h1);
    hi[2*i+1] = __halves2bfloat162(h2, h3);
    lo[2*i]   = __halves2bfloat162(l0, l1);
    lo[2*i+1] = __halves2bfloat162(l2, l3);
}

// ---------------------------------------------------------------------------
// Projection: O[m,n] = X[m,:] . W[n,:]^T, bf16 hi/lo split output.
// ---------------------------------------------------------------------------
__global__ __launch_bounds__(NTHR)
void tc_proj_kernel(const bf16* __restrict__ Ah, const bf16* __restrict__ Al,
                    const bf16* __restrict__ Bh, const bf16* __restrict__ Bl,
                    bf16* __restrict__ Oh, bf16* __restrict__ Ol)
{
    extern __shared__ char smem[];
    uint32_t sb = smem_u32(smem);
    const int bx = blockIdx.x;   // n tile
    const int by = blockIdx.y;   // m tile

    float acc[4][4][4];
    gemm_run<0>(sb,
        Ah + (size_t)by * 128 * D_, Al + (size_t)by * 128 * D_, D_,
        Bh + (size_t)bx * 128 * D_, Bl + (size_t)bx * 128 * D_, D_,
        D_ / 32, acc);

    const int tid = threadIdx.x, lane = tid & 31, wid = tid >> 5;
    const int wm = wid & 1, wn = wid >> 1;
    #pragma unroll
    for (int mi = 0; mi < 4; ++mi)
        #pragma unroll
        for (int ni = 0; ni < 4; ++ni) {
            int r0 = by * 128 + wm * 64 + mi * 16 + (lane >> 2);
            int c0 = bx * 128 + wn * 32 + ni * 8 + (lane & 3) * 2;
            #pragma unroll
            for (int half = 0; half < 2; ++half) {
                int gr = r0 + half * 8;
                float v0 = acc[mi][ni][half * 2 + 0];
                float v1 = acc[mi][ni][half * 2 + 1];
                bf16 h0 = __float2bfloat16(v0); bf16 l0 = __float2bfloat16(v0 - __bfloat162float(h0));
                bf16 h1 = __float2bfloat16(v1); bf16 l1 = __float2bfloat16(v1 - __bfloat162float(h1));
                *reinterpret_cast<__nv_bfloat162*>(Oh + (size_t)gr * D_ + c0) = __halves2bfloat162(h0, h1);
                *reinterpret_cast<__nv_bfloat162*>(Ol + (size_t)gr * D_ + c0) = __halves2bfloat162(l0, l1);
            }
        }
}

// ---------------------------------------------------------------------------
// Scores: S[b,q,k] = (Q.K^T)/32 with causal block skip + diag mask.
// ---------------------------------------------------------------------------
__global__ __launch_bounds__(NTHR)
void tc_scores_kernel()
{
    const int bx = blockIdx.x;    // key tile
    const int by = blockIdx.y;    // query tile
    if (bx > by) return;
    const int b = blockIdx.z;

    extern __shared__ char smem[];
    uint32_t sb = smem_u32(smem);

    size_t aoff = ((size_t)b * S_ + by * 128) * D_;
    size_t boff = ((size_t)b * S_ + bx * 128) * D_;
    float acc[4][4][4];
    gemm_run<0>(sb, g_qh + aoff, g_ql + aoff, D_,
                    g_kh + boff, g_kl + boff, D_, D_ / 32, acc);

    const int tid = threadIdx.x, lane = tid & 31, wid = tid >> 5;
    const int wm = wid & 1, wn = wid >> 1;
    const bool diag = (bx == by);
    const float alpha = 0.03125f;
    float* out = g_s + (size_t)b * S_ * S_;

    #pragma unroll
    for (int mi = 0; mi < 4; ++mi)
        #pragma unroll
        for (int ni = 0; ni < 4; ++ni) {
            int r0 = by * 128 + wm * 64 + mi * 16 + (lane >> 2);
            int c0 = bx * 128 + wn * 32 + ni * 8 + (lane & 3) * 2;
            #pragma unroll
            for (int half = 0; half < 2; ++half) {
                int gr = r0 + half * 8;
                float s0 = acc[mi][ni][half * 2 + 0] * alpha;
                float s1 = acc[mi][ni][half * 2 + 1] * alpha;
                if (diag) {
                    if (c0 > gr)     s0 = -CUDART_INF_F;
                    if (c0 + 1 > gr) s1 = -CUDART_INF_F;
                }
                *reinterpret_cast<float2*>(out + (size_t)gr * S_ + c0) = make_float2(s0, s1);
            }
        }
}

// ---------------------------------------------------------------------------
// Softmax over causal prefix; writes P as bf16 hi/lo split.
// ---------------------------------------------------------------------------
__global__ __launch_bounds__(256)
void softmax_split_kernel()
{
    const int q = blockIdx.x;
    const int b = blockIdx.y;
    const size_t off = (size_t)b * S_ * S_ + (size_t)q * S_;
    const float* row = g_s + off;
    const int L = ((q >> 7) + 1) << 7;
    const int tid = threadIdx.x;

    float v[8];
    float m = -CUDART_INF_F;
    #pragma unroll
    for (int j = 0; j < 8; ++j) {
        int i = tid + j * 256;
        v[j] = (i < L) ? row[i] : -CUDART_INF_F;
        m = fmaxf(m, v[j]);
    }
    #pragma unroll
    for (int o = 16; o > 0; o >>= 1) m = fmaxf(m, __shfl_xor_sync(0xFFFFFFFFu, m, o));
    __shared__ float red[8];
    if ((tid & 31) == 0) red[tid >> 5] = m;
    __syncthreads();
    float mg = red[0];
    #pragma unroll
    for (int j = 1; j < 8; ++j) mg = fmaxf(mg, red[j]);
    __syncthreads();

    float sum = 0.f;
    #pragma unroll
    for (int j = 0; j < 8; ++j) {
        int i = tid + j * 256;
        float e = (i < L) ? __expf(v[j] - mg) : 0.f;
        v[j] = e;
        sum += e;
    }
    #pragma unroll
    for (int o = 16; o > 0; o >>= 1) sum += __shfl_xor_sync(0xFFFFFFFFu, sum, o);
    if ((tid & 31) == 0) red[tid >> 5] = sum;
    __syncthreads();
    float tot = 0.f;
    #pragma unroll
    for (int j = 0; j < 8; ++j) tot += red[j];
    float inv = 1.0f / tot;

    #pragma unroll
    for (int j = 0; j < 8; ++j) {
        int i = tid + j * 256;
        if (i < L) {
            float p = v[j] * inv;
            bf16 h = __float2bfloat16(p);
            bf16 l = __float2bfloat16(p - __bfloat162float(h));
            g_ph[off + i] = h;
            g_pl[off + i] = l;
        }
    }
}

// ---------------------------------------------------------------------------
// PV: Out[b,q,d] = P[b,q,:kmax] . V[b,:kmax,d]   (B row-major -> trans ldmatrix)
// ---------------------------------------------------------------------------
__global__ __launch_bounds__(NTHR)
void tc_pv_kernel(float* __restrict__ out)
{
    const int bx = blockIdx.x;   // d tile
    const int by = blockIdx.y;   // q tile
    const int b  = blockIdx.z;

    extern __shared__ char smem[];
    uint32_t sb = smem_u32(smem);

    size_t aoff = (size_t)b * S_ * S_ + (size_t)by * 128 * S_;
    size_t boff = (size_t)b * S_ * D_ + (size_t)bx * 128;
    const int niter = (by + 1) * 4;     // kmax/32

    float acc[4][4][4];
    gemm_run<1>(sb, g_ph + aoff, g_pl + aoff, S_,
                    g_vh + boff, g_vl + boff, D_, niter, acc);

    const int tid = threadIdx.x, lane = tid & 31, wid = tid >> 5;
    const int wm = wid & 1, wn = wid >> 1;

    #pragma unroll
    for (int mi = 0; mi < 4; ++mi)
        #pragma unroll
        for (int ni = 0; ni < 4; ++ni) {
            int r0 = by * 128 + wm * 64 + mi * 16 + (lane >> 2);
            int c0 = bx * 128 + wn * 32 + ni * 8 + (lane & 3) * 2;
            #pragma unroll
            for (int half = 0; half < 2; ++half) {
                int gq = r0 + half * 8;
                *reinterpret_cast<float2*>(out + ((size_t)(b * S_ + gq)) * D_ + c0) =
                    make_float2(acc[mi][ni][half * 2 + 0], acc[mi][ni][half * 2 + 1]);
            }
        }
}

// ---------------------------------------------------------------------------
extern "C" void kernel_launch(void* const* d_in, const int* in_sizes, int n_in,
                              void* d_out, int out_size)
{
    const float* x  = (const float*)d_in[0];
    const float* wq = (const float*)d_in[1];
    const float* wk = (const float*)d_in[2];
    const float* wv = (const float*)d_in[3];
    float* out = (float*)d_out;

    bf16 *xh, *xl, *wqh, *wql, *wkh, *wkl, *wvh, *wvl;
    bf16 *qh, *ql, *kh, *kl, *vh, *vl;
    cudaGetSymbolAddress((void**)&xh,  g_xh);  cudaGetSymbolAddress((void**)&xl,  g_xl);
    cudaGetSymbolAddress((void**)&wqh, g_wqh); cudaGetSymbolAddress((void**)&wql, g_wql);
    cudaGetSymbolAddress((void**)&wkh, g_wkh); cudaGetSymbolAddress((void**)&wkl, g_wkl);
    cudaGetSymbolAddress((void**)&wvh, g_wvh); cudaGetSymbolAddress((void**)&wvl, g_wvl);
    cudaGetSymbolAddress((void**)&qh,  g_qh);  cudaGetSymbolAddress((void**)&ql,  g_ql);
    cudaGetSymbolAddress((void**)&kh,  g_kh);  cudaGetSymbolAddress((void**)&kl,  g_kl);
    cudaGetSymbolAddress((void**)&vh,  g_vh);  cudaGetSymbolAddress((void**)&vl,  g_vl);

    static bool attr_done = false;
    if (!attr_done) {
        cudaFuncSetAttribute(tc_proj_kernel,   cudaFuncAttributeMaxDynamicSharedMemorySize, SMEM_TOTAL);
        cudaFuncSetAttribute(tc_scores_kernel, cudaFuncAttributeMaxDynamicSharedMemorySize, SMEM_TOTAL);
        cudaFuncSetAttribute(tc_pv_kernel,     cudaFuncAttributeMaxDynamicSharedMemorySize, SMEM_TOTAL);
        attr_done = true;
    }

    // Split fp32 -> bf16 hi/lo
    {
        int n4 = M_ * D_ / 4;
        split_kernel<<<(n4 + 255) / 256, 256>>>((const float4*)x,
            (__nv_bfloat162*)xh, (__nv_bfloat162*)xl, n4);
        int w4 = D_ * D_ / 4;
        split_kernel<<<(w4 + 255) / 256, 256>>>((const float4*)wq,
            (__nv_bfloat162*)wqh, (__nv_bfloat162*)wql, w4);
        split_kernel<<<(w4 + 255) / 256, 256>>>((const float4*)wk,
            (__nv_bfloat162*)wkh, (__nv_bfloat162*)wkl, w4);
        split_kernel<<<(w4 + 255) / 256, 256>>>((const float4*)wv,
            (__nv_bfloat162*)wvh, (__nv_bfloat162*)wvl, w4);
    }

    // QKV projections
    dim3 gproj(D_ / 128, M_ / 128);
    tc_proj_kernel<<<gproj, NTHR, SMEM_TOTAL>>>(xh, xl, wqh, wql, qh, ql);
    tc_proj_kernel<<<gproj, NTHR, SMEM_TOTAL>>>(xh, xl, wkh, wkl, kh, kl);
    tc_proj_kernel<<<gproj, NTHR, SMEM_TOTAL>>>(xh, xl, wvh, wvl, vh, vl);

    // Scores (causal block skip + diag mask)
    dim3 gsc(S_ / 128, S_ / 128, B_);
    tc_scores_kernel<<<gsc, NTHR, SMEM_TOTAL>>>();

    // Softmax + P split
    dim3 gsm(S_, B_);
    softmax_split_kernel<<<gsm, 256>>>();

    // P @ V
    dim3 gpv(D_ / 128, S_ / 128, B_);
    tc_pv_kernel<<<gpv, NTHR, SMEM_TOTAL>>>(out);
}

// round 6
// speedup vs baseline: 2.6586x; 1.0467x over previous
#include <cuda_runtime.h>
#include <cuda_bf16.h>
#include <cstdint>
#include <math.h>
#include <math_constants.h>

#define B_ 4
#define S_ 2048
#define D_ 1024
#define M_ (B_*S_)   // 8192

typedef __nv_bfloat16 bf16;

// ---------------------------------------------------------------------------
// Scratch (__device__ globals; allocation-free)
// ---------------------------------------------------------------------------
__device__ __align__(256) bf16 g_xh[M_*D_], g_xl[M_*D_];
__device__ __align__(256) bf16 g_wqh[D_*D_], g_wql[D_*D_];
__device__ __align__(256) bf16 g_wkh[D_*D_], g_wkl[D_*D_];
__device__ __align__(256) bf16 g_wvh[D_*D_], g_wvl[D_*D_];
__device__ __align__(256) bf16 g_qh[M_*D_], g_ql[M_*D_];
__device__ __align__(256) bf16 g_kh[M_*D_], g_kl[M_*D_];
__device__ __align__(256) bf16 g_vh[M_*D_], g_vl[M_*D_];      // V natural [b][s][d]
__device__ __align__(256) float g_s[(size_t)B_*S_*S_];
__device__ __align__(256) bf16 g_ph[(size_t)B_*S_*S_], g_pl[(size_t)B_*S_*S_];

// ---------------------------------------------------------------------------
// Smem layout (dynamic). 2 stages. A tiles: 128 rows x 40 halves (pad).
// B NT tiles: 128 x 40 halves. B trans tiles (PV): 32 x 136 halves (8704B).
// All regions sized 10240B.
// ---------------------------------------------------------------------------
#define LDA_S 40
#define LDBT_S 136
#define OFF_AH(s) ((s)*10240u)
#define OFF_AL(s) (20480u + (s)*10240u)
#define OFF_BH(s) (40960u + (s)*10240u)
#define OFF_BL(s) (61440u + (s)*10240u)
#define SMEM_TOTAL 81920
#define NTHR 256

__device__ __forceinline__ uint32_t smem_u32(const void* p) {
    uint32_t a;
    asm("{ .reg .u64 t; cvta.to.shared.u64 t, %1; cvt.u32.u64 %0, t; }" : "=r"(a) : "l"(p));
    return a;
}
__device__ __forceinline__ void cpa16(uint32_t s, const void* g) {
    asm volatile("cp.async.cg.shared.global [%0], [%1], 16;" :: "r"(s), "l"(g));
}
__device__ __forceinline__ void ldm_x4(uint32_t addr, uint32_t r[4]) {
    asm volatile("ldmatrix.sync.aligned.m8n8.x4.shared.b16 {%0,%1,%2,%3}, [%4];"
        : "=r"(r[0]), "=r"(r[1]), "=r"(r[2]), "=r"(r[3]) : "r"(addr));
}
__device__ __forceinline__ void ldm_x4_t(uint32_t addr, uint32_t r[4]) {
    asm volatile("ldmatrix.sync.aligned.m8n8.x4.trans.shared.b16 {%0,%1,%2,%3}, [%4];"
        : "=r"(r[0]), "=r"(r[1]), "=r"(r[2]), "=r"(r[3]) : "r"(addr));
}
__device__ __forceinline__ void mma16816(float c[4], const uint32_t a[4], const uint32_t b[2]) {
    asm volatile("mma.sync.aligned.m16n8k16.row.col.f32.bf16.bf16.f32 "
        "{%0,%1,%2,%3}, {%4,%5,%6,%7}, {%8,%9}, {%0,%1,%2,%3};"
        : "+f"(c[0]), "+f"(c[1]), "+f"(c[2]), "+f"(c[3])
        : "r"(a[0]), "r"(a[1]), "r"(a[2]), "r"(a[3]), "r"(b[0]), "r"(b[1]));
}

// ---------------------------------------------------------------------------
// Stage load via cp.async. BT=0: B is [n][k] K-contig (NT). BT=1: B is [k][n]
// row-major (V natural layout), loaded untransposed into [32][136] tile.
// ---------------------------------------------------------------------------
template<int BT>
__device__ __forceinline__ void load_stage(uint32_t sb, int st, int tid,
    const bf16* __restrict__ Ah, const bf16* __restrict__ Al, int lda,
    const bf16* __restrict__ Bh, const bf16* __restrict__ Bl, int ldb, int k0)
{
    #pragma unroll
    for (int it = 0; it < 2; ++it) {
        int c = tid + it * NTHR;          // [0,512)
        int row = c >> 2;
        int kc  = (c & 3) << 3;           // halves
        uint32_t so = (uint32_t)((row * LDA_S + kc) * 2);
        cpa16(sb + OFF_AH(st) + so, Ah + (size_t)row * lda + k0 + kc);
        cpa16(sb + OFF_AL(st) + so, Al + (size_t)row * lda + k0 + kc);
        if (BT == 0) {
            cpa16(sb + OFF_BH(st) + so, Bh + (size_t)row * ldb + k0 + kc);
            cpa16(sb + OFF_BL(st) + so, Bl + (size_t)row * ldb + k0 + kc);
        } else {
            int br = c >> 4;              // k row [0,32)
            int bn = (c & 15) << 3;       // n halves [0,128)
            uint32_t bo = (uint32_t)((br * LDBT_S + bn) * 2);
            cpa16(sb + OFF_BH(st) + bo, Bh + (size_t)(k0 + br) * ldb + bn);
            cpa16(sb + OFF_BL(st) + bo, Bl + (size_t)(k0 + br) * ldb + bn);
        }
    }
}

// ---------------------------------------------------------------------------
// Compute one BK=32 stage: 2 k16-steps. B frags loaded once per k-step; A
// frags loaded just-in-time per 16-row block to keep register pressure low
// (target: 2 CTAs/SM).
// ---------------------------------------------------------------------------
template<int BT>
__device__ __forceinline__ void compute_stage(uint32_t sb, int st, int lane,
                                              int wm, int wn, float acc[4][4][4])
{
    const uint32_t sAh = sb + OFF_AH(st);
    const uint32_t sAl = sb + OFF_AL(st);
    const uint32_t sBh = sb + OFF_BH(st);
    const uint32_t sBl = sb + OFF_BL(st);

    #pragma unroll
    for (int ks = 0; ks < 2; ++ks) {
        uint32_t bh[4][2], bl[4][2];
        if (BT == 0) {
            int nr = (lane & 7) + ((lane >> 4) & 1) * 8;
            int kh = ks * 16 + ((lane >> 3) & 1) * 8;
            #pragma unroll
            for (int np = 0; np < 2; ++np) {
                uint32_t off = (uint32_t)(((wn * 32 + np * 16 + nr) * LDA_S + kh) * 2);
                uint32_t r[4];
                ldm_x4(sBh + off, r);
                bh[2*np][0] = r[0]; bh[2*np][1] = r[1];
                bh[2*np+1][0] = r[2]; bh[2*np+1][1] = r[3];
                ldm_x4(sBl + off, r);
                bl[2*np][0] = r[0]; bl[2*np][1] = r[1];
                bl[2*np+1][0] = r[2]; bl[2*np+1][1] = r[3];
            }
        } else {
            int kr = ks * 16 + ((lane >> 3) & 1) * 8 + (lane & 7);
            int nh = ((lane >> 4) & 1) * 8;
            #pragma unroll
            for (int np = 0; np < 2; ++np) {
                uint32_t off = (uint32_t)((kr * LDBT_S + wn * 32 + np * 16 + nh) * 2);
                uint32_t r[4];
                ldm_x4_t(sBh + off, r);
                bh[2*np][0] = r[0]; bh[2*np][1] = r[1];
                bh[2*np+1][0] = r[2]; bh[2*np+1][1] = r[3];
                ldm_x4_t(sBl + off, r);
                bl[2*np][0] = r[0]; bl[2*np][1] = r[1];
                bl[2*np+1][0] = r[2]; bl[2*np+1][1] = r[3];
            }
        }

        const int arow = wm * 64 + (lane & 15);
        const int akh  = ks * 16 + (lane >> 4) * 8;
        #pragma unroll
        for (int mi = 0; mi < 4; ++mi) {
            uint32_t ah[4], al[4];
            uint32_t off = (uint32_t)(((arow + mi * 16) * LDA_S + akh) * 2);
            ldm_x4(sAh + off, ah);
            ldm_x4(sAl + off, al);
            #pragma unroll
            for (int ni = 0; ni < 4; ++ni) {
                mma16816(acc[mi][ni], ah, bh[ni]);
                mma16816(acc[mi][ni], ah, bl[ni]);
                mma16816(acc[mi][ni], al, bh[ni]);
            }
        }
    }
}

// ---------------------------------------------------------------------------
// Full pipelined GEMM mainloop. One __syncthreads per iteration:
//   wait(load i) -> sync -> issue load(i+1) -> compute(i)
// load(i+1) overwrites the buffer of compute(i-1); the sync guarantees every
// warp finished compute(i-1) before anyone issues load(i+1). cp.async of
// stage i+1 stays in flight under compute(i).
// ---------------------------------------------------------------------------
template<int BT>
__device__ __forceinline__ void gemm_run(uint32_t sb,
    const bf16* __restrict__ Ah, const bf16* __restrict__ Al, int lda,
    const bf16* __restrict__ Bh, const bf16* __restrict__ Bl, int ldb,
    int niter, float acc[4][4][4])
{
    const int tid = threadIdx.x;
    const int lane = tid & 31, wid = tid >> 5;
    const int wm = wid & 1, wn = wid >> 1;

    #pragma unroll
    for (int mi = 0; mi < 4; ++mi)
        #pragma unroll
        for (int ni = 0; ni < 4; ++ni)
            #pragma unroll
            for (int j = 0; j < 4; ++j) acc[mi][ni][j] = 0.f;

    load_stage<BT>(sb, 0, tid, Ah, Al, lda, Bh, Bl, ldb, 0);
    asm volatile("cp.async.commit_group;" ::: "memory");

    for (int i = 0; i < niter; ++i) {
        asm volatile("cp.async.wait_group 0;" ::: "memory");
        __syncthreads();
        if (i + 1 < niter) {
            load_stage<BT>(sb, (i + 1) & 1, tid, Ah, Al, lda, Bh, Bl, ldb, (i + 1) * 32);
            asm volatile("cp.async.commit_group;" ::: "memory");
        }
        compute_stage<BT>(sb, i & 1, lane, wm, wn, acc);
    }
}

// ---------------------------------------------------------------------------
// Split: fp32 -> bf16 hi/lo
// ---------------------------------------------------------------------------
__global__ __launch_bounds__(256)
void split_kernel(const float4* __restrict__ in, __nv_bfloat162* __restrict__ hi,
                  __nv_bfloat162* __restrict__ lo, int n4)
{
    int i = blockIdx.x * 256 + threadIdx.x;
    if (i >= n4) return;
    float4 x = in[i];
    bf16 h0 = __float2bfloat16(x.x); bf16 l0 = __float2bfloat16(x.x - __bfloat162float(h0));
    bf16 h1 = __float2bfloat16(x.y); bf16 l1 = __float2bfloat16(x.y - __bfloat162float(h1));
    bf16 h2 = __float2bfloat16(x.z); bf16 l2 = __float2bfloat16(x.z - __bfloat162float(h2));
    bf16 h3 = __float2bfloat16(x.w); bf16 l3 = __float2bfloat16(x.w - __bfloat162float(h3));
    hi[2*i]   = __halves2bfloat162(h0, h1);
    hi[2*i+1] = __halves2bfloat162(h2, h3);
    lo[2*i]   = __halves2bfloat162(l0, l1);
    lo[2*i+1] = __halves2bfloat162(l2, l3);
}

// ---------------------------------------------------------------------------
// Projection: O[m,n] = X[m,:] . W[n,:]^T, bf16 hi/lo split output.
// ---------------------------------------------------------------------------
__global__ __launch_bounds__(NTHR, 2)
void tc_proj_kernel(const bf16* __restrict__ Ah, const bf16* __restrict__ Al,
                    const bf16* __restrict__ Bh, const bf16* __restrict__ Bl,
                    bf16* __restrict__ Oh, bf16* __restrict__ Ol)
{
    extern __shared__ char smem[];
    uint32_t sb = smem_u32(smem);
    const int bx = blockIdx.x;   // n tile
    const int by = blockIdx.y;   // m tile

    float acc[4][4][4];
    gemm_run<0>(sb,
        Ah + (size_t)by * 128 * D_, Al + (size_t)by * 128 * D_, D_,
        Bh + (size_t)bx * 128 * D_, Bl + (size_t)bx * 128 * D_, D_,
        D_ / 32, acc);

    const int tid = threadIdx.x, lane = tid & 31, wid = tid >> 5;
    const int wm = wid & 1, wn = wid >> 1;
    #pragma unroll
    for (int mi = 0; mi < 4; ++mi)
        #pragma unroll
        for (int ni = 0; ni < 4; ++ni) {
            int r0 = by * 128 + wm * 64 + mi * 16 + (lane >> 2);
            int c0 = bx * 128 + wn * 32 + ni * 8 + (lane & 3) * 2;
            #pragma unroll
            for (int half = 0; half < 2; ++half) {
                int gr = r0 + half * 8;
                float v0 = acc[mi][ni][half * 2 + 0];
                float v1 = acc[mi][ni][half * 2 + 1];
                bf16 h0 = __float2bfloat16(v0); bf16 l0 = __float2bfloat16(v0 - __bfloat162float(h0));
                bf16 h1 = __float2bfloat16(v1); bf16 l1 = __float2bfloat16(v1 - __bfloat162float(h1));
                *reinterpret_cast<__nv_bfloat162*>(Oh + (size_t)gr * D_ + c0) = __halves2bfloat162(h0, h1);
                *reinterpret_cast<__nv_bfloat162*>(Ol + (size_t)gr * D_ + c0) = __halves2bfloat162(l0, l1);
            }
        }
}

// ---------------------------------------------------------------------------
// Scores: S[b,q,k] = (Q.K^T)/32 with causal block skip + diag mask.
// ---------------------------------------------------------------------------
__global__ __launch_bounds__(NTHR, 2)
void tc_scores_kernel()
{
    const int bx = blockIdx.x;    // key tile
    const int by = blockIdx.y;    // query tile
    if (bx > by) return;
    const int b = blockIdx.z;

    extern __shared__ char smem[];
    uint32_t sb = smem_u32(smem);

    size_t aoff = ((size_t)b * S_ + by * 128) * D_;
    size_t boff = ((size_t)b * S_ + bx * 128) * D_;
    float acc[4][4][4];
    gemm_run<0>(sb, g_qh + aoff, g_ql + aoff, D_,
                    g_kh + boff, g_kl + boff, D_, D_ / 32, acc);

    const int tid = threadIdx.x, lane = tid & 31, wid = tid >> 5;
    const int wm = wid & 1, wn = wid >> 1;
    const bool diag = (bx == by);
    const float alpha = 0.03125f;
    float* out = g_s + (size_t)b * S_ * S_;

    #pragma unroll
    for (int mi = 0; mi < 4; ++mi)
        #pragma unroll
        for (int ni = 0; ni < 4; ++ni) {
            int r0 = by * 128 + wm * 64 + mi * 16 + (lane >> 2);
            int c0 = bx * 128 + wn * 32 + ni * 8 + (lane & 3) * 2;
            #pragma unroll
            for (int half = 0; half < 2; ++half) {
                int gr = r0 + half * 8;
                float s0 = acc[mi][ni][half * 2 + 0] * alpha;
                float s1 = acc[mi][ni][half * 2 + 1] * alpha;
                if (diag) {
                    if (c0 > gr)     s0 = -CUDART_INF_F;
                    if (c0 + 1 > gr) s1 = -CUDART_INF_F;
                }
                *reinterpret_cast<float2*>(out + (size_t)gr * S_ + c0) = make_float2(s0, s1);
            }
        }
}

// ---------------------------------------------------------------------------
// Softmax over causal prefix; writes P as bf16 hi/lo split.
// ---------------------------------------------------------------------------
__global__ __launch_bounds__(256)
void softmax_split_kernel()
{
    const int q = blockIdx.x;
    const int b = blockIdx.y;
    const size_t off = (size_t)b * S_ * S_ + (size_t)q * S_;
    const float* row = g_s + off;
    const int L = ((q >> 7) + 1) << 7;
    const int tid = threadIdx.x;

    float v[8];
    float m = -CUDART_INF_F;
    #pragma unroll
    for (int j = 0; j < 8; ++j) {
        int i = tid + j * 256;
        v[j] = (i < L) ? row[i] : -CUDART_INF_F;
        m = fmaxf(m, v[j]);
    }
    #pragma unroll
    for (int o = 16; o > 0; o >>= 1) m = fmaxf(m, __shfl_xor_sync(0xFFFFFFFFu, m, o));
    __shared__ float red[8];
    if ((tid & 31) == 0) red[tid >> 5] = m;
    __syncthreads();
    float mg = red[0];
    #pragma unroll
    for (int j = 1; j < 8; ++j) mg = fmaxf(mg, red[j]);
    __syncthreads();

    float sum = 0.f;
    #pragma unroll
    for (int j = 0; j < 8; ++j) {
        int i = tid + j * 256;
        float e = (i < L) ? __expf(v[j] - mg) : 0.f;
        v[j] = e;
        sum += e;
    }
    #pragma unroll
    for (int o = 16; o > 0; o >>= 1) sum += __shfl_xor_sync(0xFFFFFFFFu, sum, o);
    if ((tid & 31) == 0) red[tid >> 5] = sum;
    __syncthreads();
    float tot = 0.f;
    #pragma unroll
    for (int j = 0; j < 8; ++j) tot += red[j];
    float inv = 1.0f / tot;

    #pragma unroll
    for (int j = 0; j < 8; ++j) {
        int i = tid + j * 256;
        if (i < L) {
            float p = v[j] * inv;
            bf16 h = __float2bfloat16(p);
            bf16 l = __float2bfloat16(p - __bfloat162float(h));
            g_ph[off + i] = h;
            g_pl[off + i] = l;
        }
    }
}

// ---------------------------------------------------------------------------
// PV: Out[b,q,d] = P[b,q,:kmax] . V[b,:kmax,d]   (B row-major -> trans ldmatrix)
// ---------------------------------------------------------------------------
__global__ __launch_bounds__(NTHR, 2)
void tc_pv_kernel(float* __restrict__ out)
{
    const int bx = blockIdx.x;   // d tile
    const int by = blockIdx.y;   // q tile
    const int b  = blockIdx.z;

    extern __shared__ char smem[];
    uint32_t sb = smem_u32(smem);

    size_t aoff = (size_t)b * S_ * S_ + (size_t)by * 128 * S_;
    size_t boff = (size_t)b * S_ * D_ + (size_t)bx * 128;
    const int niter = (by + 1) * 4;     // kmax/32

    float acc[4][4][4];
    gemm_run<1>(sb, g_ph + aoff, g_pl + aoff, S_,
                    g_vh + boff, g_vl + boff, D_, niter, acc);

    const int tid = threadIdx.x, lane = tid & 31, wid = tid >> 5;
    const int wm = wid & 1, wn = wid >> 1;

    #pragma unroll
    for (int mi = 0; mi < 4; ++mi)
        #pragma unroll
        for (int ni = 0; ni < 4; ++ni) {
            int r0 = by * 128 + wm * 64 + mi * 16 + (lane >> 2);
            int c0 = bx * 128 + wn * 32 + ni * 8 + (lane & 3) * 2;
            #pragma unroll
            for (int half = 0; half < 2; ++half) {
                int gq = r0 + half * 8;
                *reinterpret_cast<float2*>(out + ((size_t)(b * S_ + gq)) * D_ + c0) =
                    make_float2(acc[mi][ni][half * 2 + 0], acc[mi][ni][half * 2 + 1]);
            }
        }
}

// ---------------------------------------------------------------------------
extern "C" void kernel_launch(void* const* d_in, const int* in_sizes, int n_in,
                              void* d_out, int out_size)
{
    const float* x  = (const float*)d_in[0];
    const float* wq = (const float*)d_in[1];
    const float* wk = (const float*)d_in[2];
    const float* wv = (const float*)d_in[3];
    float* out = (float*)d_out;

    bf16 *xh, *xl, *wqh, *wql, *wkh, *wkl, *wvh, *wvl;
    bf16 *qh, *ql, *kh, *kl, *vh, *vl;
    cudaGetSymbolAddress((void**)&xh,  g_xh);  cudaGetSymbolAddress((void**)&xl,  g_xl);
    cudaGetSymbolAddress((void**)&wqh, g_wqh); cudaGetSymbolAddress((void**)&wql, g_wql);
    cudaGetSymbolAddress((void**)&wkh, g_wkh); cudaGetSymbolAddress((void**)&wkl, g_wkl);
    cudaGetSymbolAddress((void**)&wvh, g_wvh); cudaGetSymbolAddress((void**)&wvl, g_wvl);
    cudaGetSymbolAddress((void**)&qh,  g_qh);  cudaGetSymbolAddress((void**)&ql,  g_ql);
    cudaGetSymbolAddress((void**)&kh,  g_kh);  cudaGetSymbolAddress((void**)&kl,  g_kl);
    cudaGetSymbolAddress((void**)&vh,  g_vh);  cudaGetSymbolAddress((void**)&vl,  g_vl);

    static bool attr_done = false;
    if (!attr_done) {
        cudaFuncSetAttribute(tc_proj_kernel,   cudaFuncAttributeMaxDynamicSharedMemorySize, SMEM_TOTAL);
        cudaFuncSetAttribute(tc_scores_kernel, cudaFuncAttributeMaxDynamicSharedMemorySize, SMEM_TOTAL);
        cudaFuncSetAttribute(tc_pv_kernel,     cudaFuncAttributeMaxDynamicSharedMemorySize, SMEM_TOTAL);
        attr_done = true;
    }

    // Split fp32 -> bf16 hi/lo
    {
        int n4 = M_ * D_ / 4;
        split_kernel<<<(n4 + 255) / 256, 256>>>((const float4*)x,
            (__nv_bfloat162*)xh, (__nv_bfloat162*)xl, n4);
        int w4 = D_ * D_ / 4;
        split_kernel<<<(w4 + 255) / 256, 256>>>((const float4*)wq,
            (__nv_bfloat162*)wqh, (__nv_bfloat162*)wql, w4);
        split_kernel<<<(w4 + 255) / 256, 256>>>((const float4*)wk,
            (__nv_bfloat162*)wkh, (__nv_bfloat162*)wkl, w4);
        split_kernel<<<(w4 + 255) / 256, 256>>>((const float4*)wv,
            (__nv_bfloat162*)wvh, (__nv_bfloat162*)wvl, w4);
    }

    // QKV projections
    dim3 gproj(D_ / 128, M_ / 128);
    tc_proj_kernel<<<gproj, NTHR, SMEM_TOTAL>>>(xh, xl, wqh, wql, qh, ql);
    tc_proj_kernel<<<gproj, NTHR, SMEM_TOTAL>>>(xh, xl, wkh, wkl, kh, kl);
    tc_proj_kernel<<<gproj, NTHR, SMEM_TOTAL>>>(xh, xl, wvh, wvl, vh, vl);

    // Scores (causal block skip + diag mask)
    dim3 gsc(S_ / 128, S_ / 128, B_);
    tc_scores_kernel<<<gsc, NTHR, SMEM_TOTAL>>>();

    // Softmax + P split
    dim3 gsm(S_, B_);
    softmax_split_kernel<<<gsm, 256>>>();

    // P @ V
    dim3 gpv(D_ / 128, S_ / 128, B_);
    tc_pv_kernel<<<gpv, NTHR, SMEM_TOTAL>>>(out);
}

// round 7
// speedup vs baseline: 2.8622x; 1.0766x over previous
#include <cuda_runtime.h>
#include <cuda_bf16.h>
#include <cstdint>
#include <math.h>
#include <math_constants.h>

#define B_ 4
#define S_ 2048
#define D_ 1024
#define M_ (B_*S_)   // 8192

typedef __nv_bfloat16 bf16;

// ---------------------------------------------------------------------------
// Scratch (__device__ globals; allocation-free)
// ---------------------------------------------------------------------------
__device__ __align__(256) bf16 g_xh[M_*D_], g_xl[M_*D_];
__device__ __align__(256) bf16 g_wqh[D_*D_], g_wql[D_*D_];
__device__ __align__(256) bf16 g_wkh[D_*D_], g_wkl[D_*D_];
__device__ __align__(256) bf16 g_wvh[D_*D_], g_wvl[D_*D_];
__device__ __align__(256) bf16 g_qh[M_*D_], g_ql[M_*D_];
__device__ __align__(256) bf16 g_kh[M_*D_], g_kl[M_*D_];
__device__ __align__(256) bf16 g_vh[M_*D_], g_vl[M_*D_];      // V natural [b][s][d]
__device__ __align__(256) float g_s[(size_t)B_*S_*S_];
__device__ __align__(256) bf16 g_ph[(size_t)B_*S_*S_], g_pl[(size_t)B_*S_*S_];

// ---------------------------------------------------------------------------
// Smem layout (dynamic). 2 stages. A tiles: 128 rows x 40 halves (pad).
// B NT tiles: 128 x 40 halves. B trans tiles (PV): 32 x 136 halves (8704B).
// All regions sized 10240B.
// ---------------------------------------------------------------------------
#define LDA_S 40
#define LDBT_S 136
#define OFF_AH(s) ((s)*10240u)
#define OFF_AL(s) (20480u + (s)*10240u)
#define OFF_BH(s) (40960u + (s)*10240u)
#define OFF_BL(s) (61440u + (s)*10240u)
#define SMEM_TOTAL 81920
#define NTHR 256

__device__ __forceinline__ uint32_t smem_u32(const void* p) {
    uint32_t a;
    asm("{ .reg .u64 t; cvta.to.shared.u64 t, %1; cvt.u32.u64 %0, t; }" : "=r"(a) : "l"(p));
    return a;
}
__device__ __forceinline__ void cpa16(uint32_t s, const void* g) {
    asm volatile("cp.async.cg.shared.global [%0], [%1], 16;" :: "r"(s), "l"(g));
}
__device__ __forceinline__ void ldm_x4(uint32_t addr, uint32_t r[4]) {
    asm volatile("ldmatrix.sync.aligned.m8n8.x4.shared.b16 {%0,%1,%2,%3}, [%4];"
        : "=r"(r[0]), "=r"(r[1]), "=r"(r[2]), "=r"(r[3]) : "r"(addr));
}
__device__ __forceinline__ void ldm_x4_t(uint32_t addr, uint32_t r[4]) {
    asm volatile("ldmatrix.sync.aligned.m8n8.x4.trans.shared.b16 {%0,%1,%2,%3}, [%4];"
        : "=r"(r[0]), "=r"(r[1]), "=r"(r[2]), "=r"(r[3]) : "r"(addr));
}
__device__ __forceinline__ void mma16816(float c[4], const uint32_t a[4], const uint32_t b[2]) {
    asm volatile("mma.sync.aligned.m16n8k16.row.col.f32.bf16.bf16.f32 "
        "{%0,%1,%2,%3}, {%4,%5,%6,%7}, {%8,%9}, {%0,%1,%2,%3};"
        : "+f"(c[0]), "+f"(c[1]), "+f"(c[2]), "+f"(c[3])
        : "r"(a[0]), "r"(a[1]), "r"(a[2]), "r"(a[3]), "r"(b[0]), "r"(b[1]));
}

// ---------------------------------------------------------------------------
// Stage load via cp.async. BT=0: B is [n][k] K-contig (NT). BT=1: B is [k][n]
// row-major (V natural layout), loaded untransposed into [32][136] tile.
// ---------------------------------------------------------------------------
template<int BT>
__device__ __forceinline__ void load_stage(uint32_t sb, int st, int tid,
    const bf16* __restrict__ Ah, const bf16* __restrict__ Al, int lda,
    const bf16* __restrict__ Bh, const bf16* __restrict__ Bl, int ldb, int k0)
{
    #pragma unroll
    for (int it = 0; it < 2; ++it) {
        int c = tid + it * NTHR;          // [0,512)
        int row = c >> 2;
        int kc  = (c & 3) << 3;           // halves
        uint32_t so = (uint32_t)((row * LDA_S + kc) * 2);
        cpa16(sb + OFF_AH(st) + so, Ah + (size_t)row * lda + k0 + kc);
        cpa16(sb + OFF_AL(st) + so, Al + (size_t)row * lda + k0 + kc);
        if (BT == 0) {
            cpa16(sb + OFF_BH(st) + so, Bh + (size_t)row * ldb + k0 + kc);
            cpa16(sb + OFF_BL(st) + so, Bl + (size_t)row * ldb + k0 + kc);
        } else {
            int br = c >> 4;              // k row [0,32)
            int bn = (c & 15) << 3;       // n halves [0,128)
            uint32_t bo = (uint32_t)((br * LDBT_S + bn) * 2);
            cpa16(sb + OFF_BH(st) + bo, Bh + (size_t)(k0 + br) * ldb + bn);
            cpa16(sb + OFF_BL(st) + bo, Bl + (size_t)(k0 + br) * ldb + bn);
        }
    }
}

// ---------------------------------------------------------------------------
// Compute one BK=32 stage: 2 k16-steps. B frags per k-step; A frags JIT per
// 16-row block to bound register pressure (2 CTAs/SM).
// ---------------------------------------------------------------------------
template<int BT>
__device__ __forceinline__ void compute_stage(uint32_t sb, int st, int lane,
                                              int wm, int wn, float acc[4][4][4])
{
    const uint32_t sAh = sb + OFF_AH(st);
    const uint32_t sAl = sb + OFF_AL(st);
    const uint32_t sBh = sb + OFF_BH(st);
    const uint32_t sBl = sb + OFF_BL(st);

    #pragma unroll
    for (int ks = 0; ks < 2; ++ks) {
        uint32_t bh[4][2], bl[4][2];
        if (BT == 0) {
            int nr = (lane & 7) + ((lane >> 4) & 1) * 8;
            int kh = ks * 16 + ((lane >> 3) & 1) * 8;
            #pragma unroll
            for (int np = 0; np < 2; ++np) {
                uint32_t off = (uint32_t)(((wn * 32 + np * 16 + nr) * LDA_S + kh) * 2);
                uint32_t r[4];
                ldm_x4(sBh + off, r);
                bh[2*np][0] = r[0]; bh[2*np][1] = r[1];
                bh[2*np+1][0] = r[2]; bh[2*np+1][1] = r[3];
                ldm_x4(sBl + off, r);
                bl[2*np][0] = r[0]; bl[2*np][1] = r[1];
                bl[2*np+1][0] = r[2]; bl[2*np+1][1] = r[3];
            }
        } else {
            int kr = ks * 16 + ((lane >> 3) & 1) * 8 + (lane & 7);
            int nh = ((lane >> 4) & 1) * 8;
            #pragma unroll
            for (int np = 0; np < 2; ++np) {
                uint32_t off = (uint32_t)((kr * LDBT_S + wn * 32 + np * 16 + nh) * 2);
                uint32_t r[4];
                ldm_x4_t(sBh + off, r);
                bh[2*np][0] = r[0]; bh[2*np][1] = r[1];
                bh[2*np+1][0] = r[2]; bh[2*np+1][1] = r[3];
                ldm_x4_t(sBl + off, r);
                bl[2*np][0] = r[0]; bl[2*np][1] = r[1];
                bl[2*np+1][0] = r[2]; bl[2*np+1][1] = r[3];
            }
        }

        const int arow = wm * 64 + (lane & 15);
        const int akh  = ks * 16 + (lane >> 4) * 8;
        #pragma unroll
        for (int mi = 0; mi < 4; ++mi) {
            uint32_t ah[4], al[4];
            uint32_t off = (uint32_t)(((arow + mi * 16) * LDA_S + akh) * 2);
            ldm_x4(sAh + off, ah);
            ldm_x4(sAl + off, al);
            #pragma unroll
            for (int ni = 0; ni < 4; ++ni) {
                mma16816(acc[mi][ni], ah, bh[ni]);
                mma16816(acc[mi][ni], ah, bl[ni]);
                mma16816(acc[mi][ni], al, bh[ni]);
            }
        }
    }
}

// ---------------------------------------------------------------------------
// Full pipelined GEMM mainloop. One __syncthreads per iteration:
//   wait(load i) -> sync -> issue load(i+1) -> compute(i)
// ---------------------------------------------------------------------------
template<int BT>
__device__ __forceinline__ void gemm_run(uint32_t sb,
    const bf16* __restrict__ Ah, const bf16* __restrict__ Al, int lda,
    const bf16* __restrict__ Bh, const bf16* __restrict__ Bl, int ldb,
    int niter, float acc[4][4][4])
{
    const int tid = threadIdx.x;
    const int lane = tid & 31, wid = tid >> 5;
    const int wm = wid & 1, wn = wid >> 1;

    #pragma unroll
    for (int mi = 0; mi < 4; ++mi)
        #pragma unroll
        for (int ni = 0; ni < 4; ++ni)
            #pragma unroll
            for (int j = 0; j < 4; ++j) acc[mi][ni][j] = 0.f;

    load_stage<BT>(sb, 0, tid, Ah, Al, lda, Bh, Bl, ldb, 0);
    asm volatile("cp.async.commit_group;" ::: "memory");

    for (int i = 0; i < niter; ++i) {
        asm volatile("cp.async.wait_group 0;" ::: "memory");
        __syncthreads();
        if (i + 1 < niter) {
            load_stage<BT>(sb, (i + 1) & 1, tid, Ah, Al, lda, Bh, Bl, ldb, (i + 1) * 32);
            asm volatile("cp.async.commit_group;" ::: "memory");
        }
        compute_stage<BT>(sb, i & 1, lane, wm, wn, acc);
    }
}

// ---------------------------------------------------------------------------
// Merged split: fp32 -> bf16 hi/lo for all 4 tensors in one launch.
// blockIdx.y selects tensor: 0=x (2M float4), 1..3=w (256K float4).
// ---------------------------------------------------------------------------
__global__ __launch_bounds__(256)
void split_all_kernel(const float4* __restrict__ x,  const float4* __restrict__ wq,
                      const float4* __restrict__ wk, const float4* __restrict__ wv,
                      __nv_bfloat162* __restrict__ xh,  __nv_bfloat162* __restrict__ xl,
                      __nv_bfloat162* __restrict__ wqh, __nv_bfloat162* __restrict__ wql,
                      __nv_bfloat162* __restrict__ wkh, __nv_bfloat162* __restrict__ wkl,
                      __nv_bfloat162* __restrict__ wvh, __nv_bfloat162* __restrict__ wvl)
{
    const int t = blockIdx.y;
    const float4* in; __nv_bfloat162 *hi, *lo; int n4;
    if (t == 0)      { in = x;  hi = xh;  lo = xl;  n4 = M_*D_/4; }
    else if (t == 1) { in = wq; hi = wqh; lo = wql; n4 = D_*D_/4; }
    else if (t == 2) { in = wk; hi = wkh; lo = wkl; n4 = D_*D_/4; }
    else             { in = wv; hi = wvh; lo = wvl; n4 = D_*D_/4; }

    int i = blockIdx.x * 256 + threadIdx.x;
    if (i >= n4) return;
    float4 v = in[i];
    bf16 h0 = __float2bfloat16(v.x); bf16 l0 = __float2bfloat16(v.x - __bfloat162float(h0));
    bf16 h1 = __float2bfloat16(v.y); bf16 l1 = __float2bfloat16(v.y - __bfloat162float(h1));
    bf16 h2 = __float2bfloat16(v.z); bf16 l2 = __float2bfloat16(v.z - __bfloat162float(h2));
    bf16 h3 = __float2bfloat16(v.w); bf16 l3 = __float2bfloat16(v.w - __bfloat162float(h3));
    hi[2*i]   = __halves2bfloat162(h0, h1);
    hi[2*i+1] = __halves2bfloat162(h2, h3);
    lo[2*i]   = __halves2bfloat162(l0, l1);
    lo[2*i+1] = __halves2bfloat162(l2, l3);
}

// ---------------------------------------------------------------------------
// Merged QKV projection: blockIdx.z selects which W / destination.
// ---------------------------------------------------------------------------
__global__ __launch_bounds__(NTHR, 2)
void tc_proj_kernel(const bf16* __restrict__ Ah, const bf16* __restrict__ Al)
{
    extern __shared__ char smem[];
    uint32_t sb = smem_u32(smem);
    const int bx = blockIdx.x;   // n tile
    const int by = blockIdx.y;   // m tile
    const int z  = blockIdx.z;

    const bf16 *Bh, *Bl;
    bf16 *Oh, *Ol;
    if (z == 0)      { Bh = g_wqh; Bl = g_wql; Oh = g_qh; Ol = g_ql; }
    else if (z == 1) { Bh = g_wkh; Bl = g_wkl; Oh = g_kh; Ol = g_kl; }
    else             { Bh = g_wvh; Bl = g_wvl; Oh = g_vh; Ol = g_vl; }

    float acc[4][4][4];
    gemm_run<0>(sb,
        Ah + (size_t)by * 128 * D_, Al + (size_t)by * 128 * D_, D_,
        Bh + (size_t)bx * 128 * D_, Bl + (size_t)bx * 128 * D_, D_,
        D_ / 32, acc);

    const int tid = threadIdx.x, lane = tid & 31, wid = tid >> 5;
    const int wm = wid & 1, wn = wid >> 1;
    #pragma unroll
    for (int mi = 0; mi < 4; ++mi)
        #pragma unroll
        for (int ni = 0; ni < 4; ++ni) {
            int r0 = by * 128 + wm * 64 + mi * 16 + (lane >> 2);
            int c0 = bx * 128 + wn * 32 + ni * 8 + (lane & 3) * 2;
            #pragma unroll
            for (int half = 0; half < 2; ++half) {
                int gr = r0 + half * 8;
                float v0 = acc[mi][ni][half * 2 + 0];
                float v1 = acc[mi][ni][half * 2 + 1];
                bf16 h0 = __float2bfloat16(v0); bf16 l0 = __float2bfloat16(v0 - __bfloat162float(h0));
                bf16 h1 = __float2bfloat16(v1); bf16 l1 = __float2bfloat16(v1 - __bfloat162float(h1));
                *reinterpret_cast<__nv_bfloat162*>(Oh + (size_t)gr * D_ + c0) = __halves2bfloat162(h0, h1);
                *reinterpret_cast<__nv_bfloat162*>(Ol + (size_t)gr * D_ + c0) = __halves2bfloat162(l0, l1);
            }
        }
}

// ---------------------------------------------------------------------------
// Scores with compact triangular launch: grid.x = 136 live blocks.
// idx -> (by, bx) with bx <= by. No dead CTAs.
// ---------------------------------------------------------------------------
__global__ __launch_bounds__(NTHR, 2)
void tc_scores_kernel()
{
    const int idx = blockIdx.x;
    int by = (int)((sqrtf(8.f * idx + 1.f) - 1.f) * 0.5f);
    while ((by + 1) * (by + 2) / 2 <= idx) ++by;
    while (by * (by + 1) / 2 > idx) --by;
    const int bx = idx - by * (by + 1) / 2;
    const int b = blockIdx.z;

    extern __shared__ char smem[];
    uint32_t sb = smem_u32(smem);

    size_t aoff = ((size_t)b * S_ + by * 128) * D_;
    size_t boff = ((size_t)b * S_ + bx * 128) * D_;
    float acc[4][4][4];
    gemm_run<0>(sb, g_qh + aoff, g_ql + aoff, D_,
                    g_kh + boff, g_kl + boff, D_, D_ / 32, acc);

    const int tid = threadIdx.x, lane = tid & 31, wid = tid >> 5;
    const int wm = wid & 1, wn = wid >> 1;
    const bool diag = (bx == by);
    const float alpha = 0.03125f;
    float* out = g_s + (size_t)b * S_ * S_;

    #pragma unroll
    for (int mi = 0; mi < 4; ++mi)
        #pragma unroll
        for (int ni = 0; ni < 4; ++ni) {
            int r0 = by * 128 + wm * 64 + mi * 16 + (lane >> 2);
            int c0 = bx * 128 + wn * 32 + ni * 8 + (lane & 3) * 2;
            #pragma unroll
            for (int half = 0; half < 2; ++half) {
                int gr = r0 + half * 8;
                float s0 = acc[mi][ni][half * 2 + 0] * alpha;
                float s1 = acc[mi][ni][half * 2 + 1] * alpha;
                if (diag) {
                    if (c0 > gr)     s0 = -CUDART_INF_F;
                    if (c0 + 1 > gr) s1 = -CUDART_INF_F;
                }
                *reinterpret_cast<float2*>(out + (size_t)gr * S_ + c0) = make_float2(s0, s1);
            }
        }
}

// ---------------------------------------------------------------------------
// Softmax over causal prefix; vectorized (float2 in, bf16x2 out h/l split).
// ---------------------------------------------------------------------------
__global__ __launch_bounds__(256)
void softmax_split_kernel()
{
    const int q = blockIdx.x;
    const int b = blockIdx.y;
    const size_t off = (size_t)b * S_ * S_ + (size_t)q * S_;
    const float2* row2 = reinterpret_cast<const float2*>(g_s + off);
    const int L2 = (((q >> 7) + 1) << 7) >> 1;   // pairs, <= 1024
    const int tid = threadIdx.x;

    float2 v[4];
    float m = -CUDART_INF_F;
    #pragma unroll
    for (int j = 0; j < 4; ++j) {
        int i = tid + j * 256;
        if (i < L2) { v[j] = row2[i]; m = fmaxf(m, fmaxf(v[j].x, v[j].y)); }
        else        { v[j] = make_float2(-CUDART_INF_F, -CUDART_INF_F); }
    }
    #pragma unroll
    for (int o = 16; o > 0; o >>= 1) m = fmaxf(m, __shfl_xor_sync(0xFFFFFFFFu, m, o));
    __shared__ float red[8];
    if ((tid & 31) == 0) red[tid >> 5] = m;
    __syncthreads();
    float mg = red[0];
    #pragma unroll
    for (int j = 1; j < 8; ++j) mg = fmaxf(mg, red[j]);
    __syncthreads();

    float sum = 0.f;
    #pragma unroll
    for (int j = 0; j < 4; ++j) {
        int i = tid + j * 256;
        if (i < L2) {
            v[j].x = __expf(v[j].x - mg);
            v[j].y = __expf(v[j].y - mg);
            sum += v[j].x + v[j].y;
        }
    }
    #pragma unroll
    for (int o = 16; o > 0; o >>= 1) sum += __shfl_xor_sync(0xFFFFFFFFu, sum, o);
    if ((tid & 31) == 0) red[tid >> 5] = sum;
    __syncthreads();
    float tot = 0.f;
    #pragma unroll
    for (int j = 0; j < 8; ++j) tot += red[j];
    float inv = 1.0f / tot;

    __nv_bfloat162* ph2 = reinterpret_cast<__nv_bfloat162*>(g_ph + off);
    __nv_bfloat162* pl2 = reinterpret_cast<__nv_bfloat162*>(g_pl + off);
    #pragma unroll
    for (int j = 0; j < 4; ++j) {
        int i = tid + j * 256;
        if (i < L2) {
            float p0 = v[j].x * inv, p1 = v[j].y * inv;
            bf16 h0 = __float2bfloat16(p0); bf16 l0 = __float2bfloat16(p0 - __bfloat162float(h0));
            bf16 h1 = __float2bfloat16(p1); bf16 l1 = __float2bfloat16(p1 - __bfloat162float(h1));
            ph2[i] = __halves2bfloat162(h0, h1);
            pl2[i] = __halves2bfloat162(l0, l1);
        }
    }
}

// ---------------------------------------------------------------------------
// PV: Out[b,q,d] = P[b,q,:kmax] . V[b,:kmax,d]. Longest q-tiles launch first.
// ---------------------------------------------------------------------------
__global__ __launch_bounds__(NTHR, 2)
void tc_pv_kernel(float* __restrict__ out)
{
    const int bx = blockIdx.x;                  // d tile
    const int by = (S_/128 - 1) - blockIdx.y;   // q tile, descending work order
    const int b  = blockIdx.z;

    extern __shared__ char smem[];
    uint32_t sb = smem_u32(smem);

    size_t aoff = (size_t)b * S_ * S_ + (size_t)by * 128 * S_;
    size_t boff = (size_t)b * S_ * D_ + (size_t)bx * 128;
    const int niter = (by + 1) * 4;     // kmax/32

    float acc[4][4][4];
    gemm_run<1>(sb, g_ph + aoff, g_pl + aoff, S_,
                    g_vh + boff, g_vl + boff, D_, niter, acc);

    const int tid = threadIdx.x, lane = tid & 31, wid = tid >> 5;
    const int wm = wid & 1, wn = wid >> 1;

    #pragma unroll
    for (int mi = 0; mi < 4; ++mi)
        #pragma unroll
        for (int ni = 0; ni < 4; ++ni) {
            int r0 = by * 128 + wm * 64 + mi * 16 + (lane >> 2);
            int c0 = bx * 128 + wn * 32 + ni * 8 + (lane & 3) * 2;
            #pragma unroll
            for (int half = 0; half < 2; ++half) {
                int gq = r0 + half * 8;
                *reinterpret_cast<float2*>(out + ((size_t)(b * S_ + gq)) * D_ + c0) =
                    make_float2(acc[mi][ni][half * 2 + 0], acc[mi][ni][half * 2 + 1]);
            }
        }
}

// ---------------------------------------------------------------------------
extern "C" void kernel_launch(void* const* d_in, const int* in_sizes, int n_in,
                              void* d_out, int out_size)
{
    const float* x  = (const float*)d_in[0];
    const float* wq = (const float*)d_in[1];
    const float* wk = (const float*)d_in[2];
    const float* wv = (const float*)d_in[3];
    float* out = (float*)d_out;

    bf16 *xh, *xl, *wqh, *wql, *wkh, *wkl, *wvh, *wvl;
    cudaGetSymbolAddress((void**)&xh,  g_xh);  cudaGetSymbolAddress((void**)&xl,  g_xl);
    cudaGetSymbolAddress((void**)&wqh, g_wqh); cudaGetSymbolAddress((void**)&wql, g_wql);
    cudaGetSymbolAddress((void**)&wkh, g_wkh); cudaGetSymbolAddress((void**)&wkl, g_wkl);
    cudaGetSymbolAddress((void**)&wvh, g_wvh); cudaGetSymbolAddress((void**)&wvl, g_wvl);

    static bool attr_done = false;
    if (!attr_done) {
        cudaFuncSetAttribute(tc_proj_kernel,   cudaFuncAttributeMaxDynamicSharedMemorySize, SMEM_TOTAL);
        cudaFuncSetAttribute(tc_scores_kernel, cudaFuncAttributeMaxDynamicSharedMemorySize, SMEM_TOTAL);
        cudaFuncSetAttribute(tc_pv_kernel,     cudaFuncAttributeMaxDynamicSharedMemorySize, SMEM_TOTAL);
        attr_done = true;
    }

    // All fp32 -> bf16 hi/lo splits in one launch
    {
        dim3 gs((M_ * D_ / 4 + 255) / 256, 4);
        split_all_kernel<<<gs, 256>>>((const float4*)x, (const float4*)wq,
            (const float4*)wk, (const float4*)wv,
            (__nv_bfloat162*)xh, (__nv_bfloat162*)xl,
            (__nv_bfloat162*)wqh, (__nv_bfloat162*)wql,
            (__nv_bfloat162*)wkh, (__nv_bfloat162*)wkl,
            (__nv_bfloat162*)wvh, (__nv_bfloat162*)wvl);
    }

    // QKV projections in one launch (z selects W/dst)
    dim3 gproj(D_ / 128, M_ / 128, 3);
    tc_proj_kernel<<<gproj, NTHR, SMEM_TOTAL>>>(xh, xl);

    // Scores: compact triangular grid (136 live blocks per batch)
    dim3 gsc(136, 1, B_);
    tc_scores_kernel<<<gsc, NTHR, SMEM_TOTAL>>>();

    // Softmax + P split
    dim3 gsm(S_, B_);
    softmax_split_kernel<<<gsm, 256>>>();

    // P @ V (longest first)
    dim3 gpv(D_ / 128, S_ / 128, B_);
    tc_pv_kernel<<<gpv, NTHR, SMEM_TOTAL>>>(out);
}

// round 8
// speedup vs baseline: 3.2096x; 1.1214x over previous
#include <cuda_runtime.h>
#include <cuda_bf16.h>
#include <cstdint>
#include <math.h>
#include <math_constants.h>

#define B_ 4
#define S_ 2048
#define D_ 1024
#define M_ (B_*S_)   // 8192

typedef __nv_bfloat16 bf16;

// ---------------------------------------------------------------------------
// Scratch (__device__ globals; allocation-free)
// ---------------------------------------------------------------------------
__device__ __align__(256) bf16 g_xh[M_*D_], g_xl[M_*D_];
__device__ __align__(256) bf16 g_wqh[D_*D_], g_wql[D_*D_];
__device__ __align__(256) bf16 g_wkh[D_*D_], g_wkl[D_*D_];
__device__ __align__(256) bf16 g_wvh[D_*D_], g_wvl[D_*D_];
__device__ __align__(256) bf16 g_qh[M_*D_], g_ql[M_*D_];
__device__ __align__(256) bf16 g_kh[M_*D_], g_kl[M_*D_];
__device__ __align__(256) bf16 g_vh[M_*D_], g_vl[M_*D_];      // V natural [b][s][d]
__device__ __align__(256) float g_s[(size_t)B_*S_*S_];
__device__ __align__(256) bf16 g_ph[(size_t)B_*S_*S_], g_pl[(size_t)B_*S_*S_];

// ---------------------------------------------------------------------------
// Smem: 3 stages. A / B-NT tiles: 128 rows x 32 halves, XOR-swizzled 64B rows
// (8192B, no padding). B-trans tiles (PV): 32 x 136 halves padded (8704B).
// Stage stride 33792B; 3 stages = 101376B; x2 CTAs = 203KB <= 228KB.
// ---------------------------------------------------------------------------
#define LDBT_S 136
#define STG 33792u
#define OFF_AH(s) ((s)*STG)
#define OFF_AL(s) ((s)*STG + 8192u)
#define OFF_BH(s) ((s)*STG + 16384u)
#define OFF_BL(s) ((s)*STG + 25088u)
#define SMEM_TOTAL (3*33792)
#define NTHR 256

// Swizzled byte offset for (row r, half-col k) in a [128][32]-half tile.
// 64B rows; 16B chunk index c16 = k>>3 XOR'd with (r>>1)&3.
// Conflict-free for cp.async 16B stores and all ldmatrix read phases.
__device__ __forceinline__ uint32_t swz(int r, int k) {
    return (uint32_t)(r * 64 + ((((k >> 3) ^ ((r >> 1) & 3)) << 4) | ((k & 7) << 1)));
}

__device__ __forceinline__ uint32_t smem_u32(const void* p) {
    uint32_t a;
    asm("{ .reg .u64 t; cvta.to.shared.u64 t, %1; cvt.u32.u64 %0, t; }" : "=r"(a) : "l"(p));
    return a;
}
__device__ __forceinline__ void cpa16(uint32_t s, const void* g) {
    asm volatile("cp.async.cg.shared.global [%0], [%1], 16;" :: "r"(s), "l"(g));
}
__device__ __forceinline__ void ldm_x4(uint32_t addr, uint32_t r[4]) {
    asm volatile("ldmatrix.sync.aligned.m8n8.x4.shared.b16 {%0,%1,%2,%3}, [%4];"
        : "=r"(r[0]), "=r"(r[1]), "=r"(r[2]), "=r"(r[3]) : "r"(addr));
}
__device__ __forceinline__ void ldm_x4_t(uint32_t addr, uint32_t r[4]) {
    asm volatile("ldmatrix.sync.aligned.m8n8.x4.trans.shared.b16 {%0,%1,%2,%3}, [%4];"
        : "=r"(r[0]), "=r"(r[1]), "=r"(r[2]), "=r"(r[3]) : "r"(addr));
}
__device__ __forceinline__ void mma16816(float c[4], const uint32_t a[4], const uint32_t b[2]) {
    asm volatile("mma.sync.aligned.m16n8k16.row.col.f32.bf16.bf16.f32 "
        "{%0,%1,%2,%3}, {%4,%5,%6,%7}, {%8,%9}, {%0,%1,%2,%3};"
        : "+f"(c[0]), "+f"(c[1]), "+f"(c[2]), "+f"(c[3])
        : "r"(a[0]), "r"(a[1]), "r"(a[2]), "r"(a[3]), "r"(b[0]), "r"(b[1]));
}

// ---------------------------------------------------------------------------
// Stage load via cp.async. BT=0: B is [n][k] K-contig (NT), swizzled tile.
// BT=1: B is [k][n] row-major (V natural), padded-136 linear tile.
// ---------------------------------------------------------------------------
template<int BT>
__device__ __forceinline__ void load_stage(uint32_t sb, int st, int tid,
    const bf16* __restrict__ Ah, const bf16* __restrict__ Al, int lda,
    const bf16* __restrict__ Bh, const bf16* __restrict__ Bl, int ldb, int k0)
{
    #pragma unroll
    for (int it = 0; it < 2; ++it) {
        int c = tid + it * NTHR;          // [0,512)
        int row = c >> 2;
        int kc  = (c & 3) << 3;           // halves
        uint32_t so = swz(row, kc);
        cpa16(sb + OFF_AH(st) + so, Ah + (size_t)row * lda + k0 + kc);
        cpa16(sb + OFF_AL(st) + so, Al + (size_t)row * lda + k0 + kc);
        if (BT == 0) {
            cpa16(sb + OFF_BH(st) + so, Bh + (size_t)row * ldb + k0 + kc);
            cpa16(sb + OFF_BL(st) + so, Bl + (size_t)row * ldb + k0 + kc);
        } else {
            int br = c >> 4;              // k row [0,32)
            int bn = (c & 15) << 3;       // n halves [0,128)
            uint32_t bo = (uint32_t)((br * LDBT_S + bn) * 2);
            cpa16(sb + OFF_BH(st) + bo, Bh + (size_t)(k0 + br) * ldb + bn);
            cpa16(sb + OFF_BL(st) + bo, Bl + (size_t)(k0 + br) * ldb + bn);
        }
    }
}

// ---------------------------------------------------------------------------
// Compute one BK=32 stage: 2 k16-steps. B frags per k-step; A frags JIT per
// 16-row block to bound register pressure (2 CTAs/SM).
// ---------------------------------------------------------------------------
template<int BT>
__device__ __forceinline__ void compute_stage(uint32_t sb, int st, int lane,
                                              int wm, int wn, float acc[4][4][4])
{
    const uint32_t sAh = sb + OFF_AH(st);
    const uint32_t sAl = sb + OFF_AL(st);
    const uint32_t sBh = sb + OFF_BH(st);
    const uint32_t sBl = sb + OFF_BL(st);

    #pragma unroll
    for (int ks = 0; ks < 2; ++ks) {
        uint32_t bh[4][2], bl[4][2];
        if (BT == 0) {
            int nr = (lane & 7) + ((lane >> 4) & 1) * 8;
            int kh = ks * 16 + ((lane >> 3) & 1) * 8;
            #pragma unroll
            for (int np = 0; np < 2; ++np) {
                uint32_t off = swz(wn * 32 + np * 16 + nr, kh);
                uint32_t r[4];
                ldm_x4(sBh + off, r);
                bh[2*np][0] = r[0]; bh[2*np][1] = r[1];
                bh[2*np+1][0] = r[2]; bh[2*np+1][1] = r[3];
                ldm_x4(sBl + off, r);
                bl[2*np][0] = r[0]; bl[2*np][1] = r[1];
                bl[2*np+1][0] = r[2]; bl[2*np+1][1] = r[3];
            }
        } else {
            int kr = ks * 16 + ((lane >> 3) & 1) * 8 + (lane & 7);
            int nh = ((lane >> 4) & 1) * 8;
            #pragma unroll
            for (int np = 0; np < 2; ++np) {
                uint32_t off = (uint32_t)((kr * LDBT_S + wn * 32 + np * 16 + nh) * 2);
                uint32_t r[4];
                ldm_x4_t(sBh + off, r);
                bh[2*np][0] = r[0]; bh[2*np][1] = r[1];
                bh[2*np+1][0] = r[2]; bh[2*np+1][1] = r[3];
                ldm_x4_t(sBl + off, r);
                bl[2*np][0] = r[0]; bl[2*np][1] = r[1];
                bl[2*np+1][0] = r[2]; bl[2*np+1][1] = r[3];
            }
        }

        const int arow = wm * 64 + (lane & 15);
        const int akh  = ks * 16 + (lane >> 4) * 8;
        #pragma unroll
        for (int mi = 0; mi < 4; ++mi) {
            uint32_t ah[4], al[4];
            uint32_t off = swz(arow + mi * 16, akh);
            ldm_x4(sAh + off, ah);
            ldm_x4(sAl + off, al);
            #pragma unroll
            for (int ni = 0; ni < 4; ++ni) {
                mma16816(acc[mi][ni], ah, bh[ni]);
                mma16816(acc[mi][ni], ah, bl[ni]);
                mma16816(acc[mi][ni], al, bh[ni]);
            }
        }
    }
}

// ---------------------------------------------------------------------------
// 3-stage pipelined mainloop, one __syncthreads per iteration.
//   wait(stage i ready) -> sync -> issue load(i+2) -> compute(i)
// load(i+2) reuses the buffer of compute(i-1); sync orders that reuse.
// Requires niter >= 2 (min here is 4).
// ---------------------------------------------------------------------------
template<int BT>
__device__ __forceinline__ void gemm_run(uint32_t sb,
    const bf16* __restrict__ Ah, const bf16* __restrict__ Al, int lda,
    const bf16* __restrict__ Bh, const bf16* __restrict__ Bl, int ldb,
    int niter, float acc[4][4][4])
{
    const int tid = threadIdx.x;
    const int lane = tid & 31, wid = tid >> 5;
    const int wm = wid & 1, wn = wid >> 1;

    #pragma unroll
    for (int mi = 0; mi < 4; ++mi)
        #pragma unroll
        for (int ni = 0; ni < 4; ++ni)
            #pragma unroll
            for (int j = 0; j < 4; ++j) acc[mi][ni][j] = 0.f;

    load_stage<BT>(sb, 0, tid, Ah, Al, lda, Bh, Bl, ldb, 0);
    asm volatile("cp.async.commit_group;" ::: "memory");
    load_stage<BT>(sb, 1, tid, Ah, Al, lda, Bh, Bl, ldb, 32);
    asm volatile("cp.async.commit_group;" ::: "memory");

    int st = 0;   // stage slot of iteration i
    for (int i = 0; i < niter; ++i) {
        if (i + 1 < niter) asm volatile("cp.async.wait_group 1;" ::: "memory");
        else               asm volatile("cp.async.wait_group 0;" ::: "memory");
        __syncthreads();
        if (i + 2 < niter) {
            int slot = st + 2 >= 3 ? st - 1 : st + 2;
            load_stage<BT>(sb, slot, tid, Ah, Al, lda, Bh, Bl, ldb, (i + 2) * 32);
            asm volatile("cp.async.commit_group;" ::: "memory");
        }
        compute_stage<BT>(sb, st, lane, wm, wn, acc);
        st = (st == 2) ? 0 : st + 1;
    }
}

// ---------------------------------------------------------------------------
// Merged split: fp32 -> bf16 hi/lo for all 4 tensors in one launch.
// ---------------------------------------------------------------------------
__global__ __launch_bounds__(256)
void split_all_kernel(const float4* __restrict__ x,  const float4* __restrict__ wq,
                      const float4* __restrict__ wk, const float4* __restrict__ wv,
                      __nv_bfloat162* __restrict__ xh,  __nv_bfloat162* __restrict__ xl,
                      __nv_bfloat162* __restrict__ wqh, __nv_bfloat162* __restrict__ wql,
                      __nv_bfloat162* __restrict__ wkh, __nv_bfloat162* __restrict__ wkl,
                      __nv_bfloat162* __restrict__ wvh, __nv_bfloat162* __restrict__ wvl)
{
    const int t = blockIdx.y;
    const float4* in; __nv_bfloat162 *hi, *lo; int n4;
    if (t == 0)      { in = x;  hi = xh;  lo = xl;  n4 = M_*D_/4; }
    else if (t == 1) { in = wq; hi = wqh; lo = wql; n4 = D_*D_/4; }
    else if (t == 2) { in = wk; hi = wkh; lo = wkl; n4 = D_*D_/4; }
    else             { in = wv; hi = wvh; lo = wvl; n4 = D_*D_/4; }

    int i = blockIdx.x * 256 + threadIdx.x;
    if (i >= n4) return;
    float4 v = in[i];
    bf16 h0 = __float2bfloat16(v.x); bf16 l0 = __float2bfloat16(v.x - __bfloat162float(h0));
    bf16 h1 = __float2bfloat16(v.y); bf16 l1 = __float2bfloat16(v.y - __bfloat162float(h1));
    bf16 h2 = __float2bfloat16(v.z); bf16 l2 = __float2bfloat16(v.z - __bfloat162float(h2));
    bf16 h3 = __float2bfloat16(v.w); bf16 l3 = __float2bfloat16(v.w - __bfloat162float(h3));
    hi[2*i]   = __halves2bfloat162(h0, h1);
    hi[2*i+1] = __halves2bfloat162(h2, h3);
    lo[2*i]   = __halves2bfloat162(l0, l1);
    lo[2*i+1] = __halves2bfloat162(l2, l3);
}

// ---------------------------------------------------------------------------
// Merged QKV projection: blockIdx.z selects which W / destination.
// ---------------------------------------------------------------------------
__global__ __launch_bounds__(NTHR, 2)
void tc_proj_kernel(const bf16* __restrict__ Ah, const bf16* __restrict__ Al)
{
    extern __shared__ char smem[];
    uint32_t sb = smem_u32(smem);
    const int bx = blockIdx.x;   // n tile
    const int by = blockIdx.y;   // m tile
    const int z  = blockIdx.z;

    const bf16 *Bh, *Bl;
    bf16 *Oh, *Ol;
    if (z == 0)      { Bh = g_wqh; Bl = g_wql; Oh = g_qh; Ol = g_ql; }
    else if (z == 1) { Bh = g_wkh; Bl = g_wkl; Oh = g_kh; Ol = g_kl; }
    else             { Bh = g_wvh; Bl = g_wvl; Oh = g_vh; Ol = g_vl; }

    float acc[4][4][4];
    gemm_run<0>(sb,
        Ah + (size_t)by * 128 * D_, Al + (size_t)by * 128 * D_, D_,
        Bh + (size_t)bx * 128 * D_, Bl + (size_t)bx * 128 * D_, D_,
        D_ / 32, acc);

    const int tid = threadIdx.x, lane = tid & 31, wid = tid >> 5;
    const int wm = wid & 1, wn = wid >> 1;
    #pragma unroll
    for (int mi = 0; mi < 4; ++mi)
        #pragma unroll
        for (int ni = 0; ni < 4; ++ni) {
            int r0 = by * 128 + wm * 64 + mi * 16 + (lane >> 2);
            int c0 = bx * 128 + wn * 32 + ni * 8 + (lane & 3) * 2;
            #pragma unroll
            for (int half = 0; half < 2; ++half) {
                int gr = r0 + half * 8;
                float v0 = acc[mi][ni][half * 2 + 0];
                float v1 = acc[mi][ni][half * 2 + 1];
                bf16 h0 = __float2bfloat16(v0); bf16 l0 = __float2bfloat16(v0 - __bfloat162float(h0));
                bf16 h1 = __float2bfloat16(v1); bf16 l1 = __float2bfloat16(v1 - __bfloat162float(h1));
                *reinterpret_cast<__nv_bfloat162*>(Oh + (size_t)gr * D_ + c0) = __halves2bfloat162(h0, h1);
                *reinterpret_cast<__nv_bfloat162*>(Ol + (size_t)gr * D_ + c0) = __halves2bfloat162(l0, l1);
            }
        }
}

// ---------------------------------------------------------------------------
// Scores with compact triangular launch: grid.x = 136 live blocks.
// ---------------------------------------------------------------------------
__global__ __launch_bounds__(NTHR, 2)
void tc_scores_kernel()
{
    const int idx = blockIdx.x;
    int by = (int)((sqrtf(8.f * idx + 1.f) - 1.f) * 0.5f);
    while ((by + 1) * (by + 2) / 2 <= idx) ++by;
    while (by * (by + 1) / 2 > idx) --by;
    const int bx = idx - by * (by + 1) / 2;
    const int b = blockIdx.z;

    extern __shared__ char smem[];
    uint32_t sb = smem_u32(smem);

    size_t aoff = ((size_t)b * S_ + by * 128) * D_;
    size_t boff = ((size_t)b * S_ + bx * 128) * D_;
    float acc[4][4][4];
    gemm_run<0>(sb, g_qh + aoff, g_ql + aoff, D_,
                    g_kh + boff, g_kl + boff, D_, D_ / 32, acc);

    const int tid = threadIdx.x, lane = tid & 31, wid = tid >> 5;
    const int wm = wid & 1, wn = wid >> 1;
    const bool diag = (bx == by);
    const float alpha = 0.03125f;
    float* out = g_s + (size_t)b * S_ * S_;

    #pragma unroll
    for (int mi = 0; mi < 4; ++mi)
        #pragma unroll
        for (int ni = 0; ni < 4; ++ni) {
            int r0 = by * 128 + wm * 64 + mi * 16 + (lane >> 2);
            int c0 = bx * 128 + wn * 32 + ni * 8 + (lane & 3) * 2;
            #pragma unroll
            for (int half = 0; half < 2; ++half) {
                int gr = r0 + half * 8;
                float s0 = acc[mi][ni][half * 2 + 0] * alpha;
                float s1 = acc[mi][ni][half * 2 + 1] * alpha;
                if (diag) {
                    if (c0 > gr)     s0 = -CUDART_INF_F;
                    if (c0 + 1 > gr) s1 = -CUDART_INF_F;
                }
                *reinterpret_cast<float2*>(out + (size_t)gr * S_ + c0) = make_float2(s0, s1);
            }
        }
}

// ---------------------------------------------------------------------------
// Softmax over causal prefix; vectorized (float2 in, bf16x2 out h/l split).
// ---------------------------------------------------------------------------
__global__ __launch_bounds__(256)
void softmax_split_kernel()
{
    const int q = blockIdx.x;
    const int b = blockIdx.y;
    const size_t off = (size_t)b * S_ * S_ + (size_t)q * S_;
    const float2* row2 = reinterpret_cast<const float2*>(g_s + off);
    const int L2 = (((q >> 7) + 1) << 7) >> 1;   // pairs, <= 1024
    const int tid = threadIdx.x;

    float2 v[4];
    float m = -CUDART_INF_F;
    #pragma unroll
    for (int j = 0; j < 4; ++j) {
        int i = tid + j * 256;
        if (i < L2) { v[j] = row2[i]; m = fmaxf(m, fmaxf(v[j].x, v[j].y)); }
        else        { v[j] = make_float2(-CUDART_INF_F, -CUDART_INF_F); }
    }
    #pragma unroll
    for (int o = 16; o > 0; o >>= 1) m = fmaxf(m, __shfl_xor_sync(0xFFFFFFFFu, m, o));
    __shared__ float red[8];
    if ((tid & 31) == 0) red[tid >> 5] = m;
    __syncthreads();
    float mg = red[0];
    #pragma unroll
    for (int j = 1; j < 8; ++j) mg = fmaxf(mg, red[j]);
    __syncthreads();

    float sum = 0.f;
    #pragma unroll
    for (int j = 0; j < 4; ++j) {
        int i = tid + j * 256;
        if (i < L2) {
            v[j].x = __expf(v[j].x - mg);
            v[j].y = __expf(v[j].y - mg);
            sum += v[j].x + v[j].y;
        }
    }
    #pragma unroll
    for (int o = 16; o > 0; o >>= 1) sum += __shfl_xor_sync(0xFFFFFFFFu, sum, o);
    if ((tid & 31) == 0) red[tid >> 5] = sum;
    __syncthreads();
    float tot = 0.f;
    #pragma unroll
    for (int j = 0; j < 8; ++j) tot += red[j];
    float inv = 1.0f / tot;

    __nv_bfloat162* ph2 = reinterpret_cast<__nv_bfloat162*>(g_ph + off);
    __nv_bfloat162* pl2 = reinterpret_cast<__nv_bfloat162*>(g_pl + off);
    #pragma unroll
    for (int j = 0; j < 4; ++j) {
        int i = tid + j * 256;
        if (i < L2) {
            float p0 = v[j].x * inv, p1 = v[j].y * inv;
            bf16 h0 = __float2bfloat16(p0); bf16 l0 = __float2bfloat16(p0 - __bfloat162float(h0));
            bf16 h1 = __float2bfloat16(p1); bf16 l1 = __float2bfloat16(p1 - __bfloat162float(h1));
            ph2[i] = __halves2bfloat162(h0, h1);
            pl2[i] = __halves2bfloat162(l0, l1);
        }
    }
}

// ---------------------------------------------------------------------------
// PV: Out[b,q,d] = P[b,q,:kmax] . V[b,:kmax,d]. Longest q-tiles launch first.
// ---------------------------------------------------------------------------
__global__ __launch_bounds__(NTHR, 2)
void tc_pv_kernel(float* __restrict__ out)
{
    const int bx = blockIdx.x;                  // d tile
    const int by = (S_/128 - 1) - blockIdx.y;   // q tile, descending work order
    const int b  = blockIdx.z;

    extern __shared__ char smem[];
    uint32_t sb = smem_u32(smem);

    size_t aoff = (size_t)b * S_ * S_ + (size_t)by * 128 * S_;
    size_t boff = (size_t)b * S_ * D_ + (size_t)bx * 128;
    const int niter = (by + 1) * 4;     // kmax/32

    float acc[4][4][4];
    gemm_run<1>(sb, g_ph + aoff, g_pl + aoff, S_,
                    g_vh + boff, g_vl + boff, D_, niter, acc);

    const int tid = threadIdx.x, lane = tid & 31, wid = tid >> 5;
    const int wm = wid & 1, wn = wid >> 1;

    #pragma unroll
    for (int mi = 0; mi < 4; ++mi)
        #pragma unroll
        for (int ni = 0; ni < 4; ++ni) {
            int r0 = by * 128 + wm * 64 + mi * 16 + (lane >> 2);
            int c0 = bx * 128 + wn * 32 + ni * 8 + (lane & 3) * 2;
            #pragma unroll
            for (int half = 0; half < 2; ++half) {
                int gq = r0 + half * 8;
                *reinterpret_cast<float2*>(out + ((size_t)(b * S_ + gq)) * D_ + c0) =
                    make_float2(acc[mi][ni][half * 2 + 0], acc[mi][ni][half * 2 + 1]);
            }
        }
}

// ---------------------------------------------------------------------------
extern "C" void kernel_launch(void* const* d_in, const int* in_sizes, int n_in,
                              void* d_out, int out_size)
{
    const float* x  = (const float*)d_in[0];
    const float* wq = (const float*)d_in[1];
    const float* wk = (const float*)d_in[2];
    const float* wv = (const float*)d_in[3];
    float* out = (float*)d_out;

    bf16 *xh, *xl, *wqh, *wql, *wkh, *wkl, *wvh, *wvl;
    cudaGetSymbolAddress((void**)&xh,  g_xh);  cudaGetSymbolAddress((void**)&xl,  g_xl);
    cudaGetSymbolAddress((void**)&wqh, g_wqh); cudaGetSymbolAddress((void**)&wql, g_wql);
    cudaGetSymbolAddress((void**)&wkh, g_wkh); cudaGetSymbolAddress((void**)&wkl, g_wkl);
    cudaGetSymbolAddress((void**)&wvh, g_wvh); cudaGetSymbolAddress((void**)&wvl, g_wvl);

    static bool attr_done = false;
    if (!attr_done) {
        cudaFuncSetAttribute(tc_proj_kernel,   cudaFuncAttributeMaxDynamicSharedMemorySize, SMEM_TOTAL);
        cudaFuncSetAttribute(tc_scores_kernel, cudaFuncAttributeMaxDynamicSharedMemorySize, SMEM_TOTAL);
        cudaFuncSetAttribute(tc_pv_kernel,     cudaFuncAttributeMaxDynamicSharedMemorySize, SMEM_TOTAL);
        attr_done = true;
    }

    // All fp32 -> bf16 hi/lo splits in one launch
    {
        dim3 gs((M_ * D_ / 4 + 255) / 256, 4);
        split_all_kernel<<<gs, 256>>>((const float4*)x, (const float4*)wq,
            (const float4*)wk, (const float4*)wv,
            (__nv_bfloat162*)xh, (__nv_bfloat162*)xl,
            (__nv_bfloat162*)wqh, (__nv_bfloat162*)wql,
            (__nv_bfloat162*)wkh, (__nv_bfloat162*)wkl,
            (__nv_bfloat162*)wvh, (__nv_bfloat162*)wvl);
    }

    // QKV projections in one launch (z selects W/dst)
    dim3 gproj(D_ / 128, M_ / 128, 3);
    tc_proj_kernel<<<gproj, NTHR, SMEM_TOTAL>>>(xh, xl);

    // Scores: compact triangular grid (136 live blocks per batch)
    dim3 gsc(136, 1, B_);
    tc_scores_kernel<<<gsc, NTHR, SMEM_TOTAL>>>();

    // Softmax + P split
    dim3 gsm(S_, B_);
    softmax_split_kernel<<<gsm, 256>>>();

    // P @ V (longest first)
    dim3 gpv(D_ / 128, S_ / 128, B_);
    tc_pv_kernel<<<gpv, NTHR, SMEM_TOTAL>>>(out);
}

// round 9
// speedup vs baseline: 3.3693x; 1.0498x over previous
#include <cuda_runtime.h>
#include <cuda_bf16.h>
#include <cstdint>
#include <math.h>
#include <math_constants.h>

#define B_ 4
#define S_ 2048
#define D_ 1024
#define M_ (B_*S_)   // 8192

typedef __nv_bfloat16 bf16;

// ---------------------------------------------------------------------------
// Scratch (__device__ globals; allocation-free)
// ---------------------------------------------------------------------------
__device__ __align__(256) bf16 g_xh[M_*D_], g_xl[M_*D_];
__device__ __align__(256) bf16 g_wqh[D_*D_], g_wql[D_*D_];
__device__ __align__(256) bf16 g_wkh[D_*D_], g_wkl[D_*D_];
__device__ __align__(256) bf16 g_wvh[D_*D_], g_wvl[D_*D_];
__device__ __align__(256) bf16 g_qh[M_*D_], g_ql[M_*D_];
__device__ __align__(256) bf16 g_kh[M_*D_], g_kl[M_*D_];
__device__ __align__(256) bf16 g_vh[M_*D_], g_vl[M_*D_];      // V natural [b][s][d]
__device__ __align__(256) float g_s[(size_t)B_*S_*S_];        // scores; then PV split-K partials
__device__ __align__(256) bf16 g_ph[(size_t)B_*S_*S_], g_pl[(size_t)B_*S_*S_];

// PV schedule: 24 entries per (b,bx), descending niter for work-steal packing.
// piece: -1 = full tile, 0 = lower k-half (-> scratch), 1 = upper k-half (-> out)
__device__ const int d_pv_by[24]    = {15,15,7,14,14,13,13,6,12,12,11,11,5,10,10,9,9,4,8,8,3,2,1,0};
__device__ const int d_pv_piece[24] = { 0, 1,-1, 0, 1, 0, 1,-1, 0, 1, 0, 1,-1, 0, 1,0,1,-1,0,1,-1,-1,-1,-1};

// ---------------------------------------------------------------------------
// Smem: 3 stages. A / B-NT tiles: 128 rows x 32 halves, XOR-swizzled 64B rows
// (8192B). B-trans tiles (PV): 32 x 136 halves padded (8704B).
// Stage stride 33792B; 3 stages x 2 CTAs = 203KB <= 228KB.
// ---------------------------------------------------------------------------
#define LDBT_S 136
#define STG 33792u
#define OFF_AH(s) ((s)*STG)
#define OFF_AL(s) ((s)*STG + 8192u)
#define OFF_BH(s) ((s)*STG + 16384u)
#define OFF_BL(s) ((s)*STG + 25088u)
#define SMEM_TOTAL (3*33792)
#define NTHR 256

__device__ __forceinline__ uint32_t swz(int r, int k) {
    return (uint32_t)(r * 64 + ((((k >> 3) ^ ((r >> 1) & 3)) << 4) | ((k & 7) << 1)));
}
__device__ __forceinline__ uint32_t smem_u32(const void* p) {
    uint32_t a;
    asm("{ .reg .u64 t; cvta.to.shared.u64 t, %1; cvt.u32.u64 %0, t; }" : "=r"(a) : "l"(p));
    return a;
}
__device__ __forceinline__ void cpa16(uint32_t s, const void* g) {
    asm volatile("cp.async.cg.shared.global [%0], [%1], 16;" :: "r"(s), "l"(g));
}
__device__ __forceinline__ void ldm_x4(uint32_t addr, uint32_t r[4]) {
    asm volatile("ldmatrix.sync.aligned.m8n8.x4.shared.b16 {%0,%1,%2,%3}, [%4];"
        : "=r"(r[0]), "=r"(r[1]), "=r"(r[2]), "=r"(r[3]) : "r"(addr));
}
__device__ __forceinline__ void ldm_x4_t(uint32_t addr, uint32_t r[4]) {
    asm volatile("ldmatrix.sync.aligned.m8n8.x4.trans.shared.b16 {%0,%1,%2,%3}, [%4];"
        : "=r"(r[0]), "=r"(r[1]), "=r"(r[2]), "=r"(r[3]) : "r"(addr));
}
__device__ __forceinline__ void mma16816(float c[4], const uint32_t a[4], const uint32_t b[2]) {
    asm volatile("mma.sync.aligned.m16n8k16.row.col.f32.bf16.bf16.f32 "
        "{%0,%1,%2,%3}, {%4,%5,%6,%7}, {%8,%9}, {%0,%1,%2,%3};"
        : "+f"(c[0]), "+f"(c[1]), "+f"(c[2]), "+f"(c[3])
        : "r"(a[0]), "r"(a[1]), "r"(a[2]), "r"(a[3]), "r"(b[0]), "r"(b[1]));
}

// ---------------------------------------------------------------------------
template<int BT>
__device__ __forceinline__ void load_stage(uint32_t sb, int st, int tid,
    const bf16* __restrict__ Ah, const bf16* __restrict__ Al, int lda,
    const bf16* __restrict__ Bh, const bf16* __restrict__ Bl, int ldb, int k0)
{
    #pragma unroll
    for (int it = 0; it < 2; ++it) {
        int c = tid + it * NTHR;          // [0,512)
        int row = c >> 2;
        int kc  = (c & 3) << 3;           // halves
        uint32_t so = swz(row, kc);
        cpa16(sb + OFF_AH(st) + so, Ah + (size_t)row * lda + k0 + kc);
        cpa16(sb + OFF_AL(st) + so, Al + (size_t)row * lda + k0 + kc);
        if (BT == 0) {
            cpa16(sb + OFF_BH(st) + so, Bh + (size_t)row * ldb + k0 + kc);
            cpa16(sb + OFF_BL(st) + so, Bl + (size_t)row * ldb + k0 + kc);
        } else {
            int br = c >> 4;              // k row [0,32)
            int bn = (c & 15) << 3;       // n halves [0,128)
            uint32_t bo = (uint32_t)((br * LDBT_S + bn) * 2);
            cpa16(sb + OFF_BH(st) + bo, Bh + (size_t)(k0 + br) * ldb + bn);
            cpa16(sb + OFF_BL(st) + bo, Bl + (size_t)(k0 + br) * ldb + bn);
        }
    }
}

template<int BT>
__device__ __forceinline__ void compute_stage(uint32_t sb, int st, int lane,
                                              int wm, int wn, float acc[4][4][4])
{
    const uint32_t sAh = sb + OFF_AH(st);
    const uint32_t sAl = sb + OFF_AL(st);
    const uint32_t sBh = sb + OFF_BH(st);
    const uint32_t sBl = sb + OFF_BL(st);

    #pragma unroll
    for (int ks = 0; ks < 2; ++ks) {
        uint32_t bh[4][2], bl[4][2];
        if (BT == 0) {
            int nr = (lane & 7) + ((lane >> 4) & 1) * 8;
            int kh = ks * 16 + ((lane >> 3) & 1) * 8;
            #pragma unroll
            for (int np = 0; np < 2; ++np) {
                uint32_t off = swz(wn * 32 + np * 16 + nr, kh);
                uint32_t r[4];
                ldm_x4(sBh + off, r);
                bh[2*np][0] = r[0]; bh[2*np][1] = r[1];
                bh[2*np+1][0] = r[2]; bh[2*np+1][1] = r[3];
                ldm_x4(sBl + off, r);
                bl[2*np][0] = r[0]; bl[2*np][1] = r[1];
                bl[2*np+1][0] = r[2]; bl[2*np+1][1] = r[3];
            }
        } else {
            int kr = ks * 16 + ((lane >> 3) & 1) * 8 + (lane & 7);
            int nh = ((lane >> 4) & 1) * 8;
            #pragma unroll
            for (int np = 0; np < 2; ++np) {
                uint32_t off = (uint32_t)((kr * LDBT_S + wn * 32 + np * 16 + nh) * 2);
                uint32_t r[4];
                ldm_x4_t(sBh + off, r);
                bh[2*np][0] = r[0]; bh[2*np][1] = r[1];
                bh[2*np+1][0] = r[2]; bh[2*np+1][1] = r[3];
                ldm_x4_t(sBl + off, r);
                bl[2*np][0] = r[0]; bl[2*np][1] = r[1];
                bl[2*np+1][0] = r[2]; bl[2*np+1][1] = r[3];
            }
        }

        const int arow = wm * 64 + (lane & 15);
        const int akh  = ks * 16 + (lane >> 4) * 8;
        #pragma unroll
        for (int mi = 0; mi < 4; ++mi) {
            uint32_t ah[4], al[4];
            uint32_t off = swz(arow + mi * 16, akh);
            ldm_x4(sAh + off, ah);
            ldm_x4(sAl + off, al);
            #pragma unroll
            for (int ni = 0; ni < 4; ++ni) {
                mma16816(acc[mi][ni], ah, bh[ni]);
                mma16816(acc[mi][ni], ah, bl[ni]);
                mma16816(acc[mi][ni], al, bh[ni]);
            }
        }
    }
}

// 3-stage pipelined mainloop; one __syncthreads per iteration. niter >= 2.
template<int BT>
__device__ __forceinline__ void gemm_run(uint32_t sb,
    const bf16* __restrict__ Ah, const bf16* __restrict__ Al, int lda,
    const bf16* __restrict__ Bh, const bf16* __restrict__ Bl, int ldb,
    int niter, float acc[4][4][4])
{
    const int tid = threadIdx.x;
    const int lane = tid & 31, wid = tid >> 5;
    const int wm = wid & 1, wn = wid >> 1;

    #pragma unroll
    for (int mi = 0; mi < 4; ++mi)
        #pragma unroll
        for (int ni = 0; ni < 4; ++ni)
            #pragma unroll
            for (int j = 0; j < 4; ++j) acc[mi][ni][j] = 0.f;

    load_stage<BT>(sb, 0, tid, Ah, Al, lda, Bh, Bl, ldb, 0);
    asm volatile("cp.async.commit_group;" ::: "memory");
    load_stage<BT>(sb, 1, tid, Ah, Al, lda, Bh, Bl, ldb, 32);
    asm volatile("cp.async.commit_group;" ::: "memory");

    int st = 0;
    for (int i = 0; i < niter; ++i) {
        if (i + 1 < niter) asm volatile("cp.async.wait_group 1;" ::: "memory");
        else               asm volatile("cp.async.wait_group 0;" ::: "memory");
        __syncthreads();
        if (i + 2 < niter) {
            int slot = st + 2 >= 3 ? st - 1 : st + 2;
            load_stage<BT>(sb, slot, tid, Ah, Al, lda, Bh, Bl, ldb, (i + 2) * 32);
            asm volatile("cp.async.commit_group;" ::: "memory");
        }
        compute_stage<BT>(sb, st, lane, wm, wn, acc);
        st = (st == 2) ? 0 : st + 1;
    }
}

// ---------------------------------------------------------------------------
// Merged split: fp32 -> bf16 hi/lo for all 4 tensors in one launch.
// ---------------------------------------------------------------------------
__global__ __launch_bounds__(256)
void split_all_kernel(const float4* __restrict__ x,  const float4* __restrict__ wq,
                      const float4* __restrict__ wk, const float4* __restrict__ wv,
                      __nv_bfloat162* __restrict__ xh,  __nv_bfloat162* __restrict__ xl,
                      __nv_bfloat162* __restrict__ wqh, __nv_bfloat162* __restrict__ wql,
                      __nv_bfloat162* __restrict__ wkh, __nv_bfloat162* __restrict__ wkl,
                      __nv_bfloat162* __restrict__ wvh, __nv_bfloat162* __restrict__ wvl)
{
    const int t = blockIdx.y;
    const float4* in; __nv_bfloat162 *hi, *lo; int n4;
    if (t == 0)      { in = x;  hi = xh;  lo = xl;  n4 = M_*D_/4; }
    else if (t == 1) { in = wq; hi = wqh; lo = wql; n4 = D_*D_/4; }
    else if (t == 2) { in = wk; hi = wkh; lo = wkl; n4 = D_*D_/4; }
    else             { in = wv; hi = wvh; lo = wvl; n4 = D_*D_/4; }

    int i = blockIdx.x * 256 + threadIdx.x;
    if (i >= n4) return;
    float4 v = in[i];
    bf16 h0 = __float2bfloat16(v.x); bf16 l0 = __float2bfloat16(v.x - __bfloat162float(h0));
    bf16 h1 = __float2bfloat16(v.y); bf16 l1 = __float2bfloat16(v.y - __bfloat162float(h1));
    bf16 h2 = __float2bfloat16(v.z); bf16 l2 = __float2bfloat16(v.z - __bfloat162float(h2));
    bf16 h3 = __float2bfloat16(v.w); bf16 l3 = __float2bfloat16(v.w - __bfloat162float(h3));
    hi[2*i]   = __halves2bfloat162(h0, h1);
    hi[2*i+1] = __halves2bfloat162(h2, h3);
    lo[2*i]   = __halves2bfloat162(l0, l1);
    lo[2*i+1] = __halves2bfloat162(l2, l3);
}

// ---------------------------------------------------------------------------
// Merged QKV projection: blockIdx.z selects which W / destination.
// ---------------------------------------------------------------------------
__global__ __launch_bounds__(NTHR, 2)
void tc_proj_kernel(const bf16* __restrict__ Ah, const bf16* __restrict__ Al)
{
    extern __shared__ char smem[];
    uint32_t sb = smem_u32(smem);
    const int bx = blockIdx.x;   // n tile
    const int by = blockIdx.y;   // m tile
    const int z  = blockIdx.z;

    const bf16 *Bh, *Bl;
    bf16 *Oh, *Ol;
    if (z == 0)      { Bh = g_wqh; Bl = g_wql; Oh = g_qh; Ol = g_ql; }
    else if (z == 1) { Bh = g_wkh; Bl = g_wkl; Oh = g_kh; Ol = g_kl; }
    else             { Bh = g_wvh; Bl = g_wvl; Oh = g_vh; Ol = g_vl; }

    float acc[4][4][4];
    gemm_run<0>(sb,
        Ah + (size_t)by * 128 * D_, Al + (size_t)by * 128 * D_, D_,
        Bh + (size_t)bx * 128 * D_, Bl + (size_t)bx * 128 * D_, D_,
        D_ / 32, acc);

    const int tid = threadIdx.x, lane = tid & 31, wid = tid >> 5;
    const int wm = wid & 1, wn = wid >> 1;
    #pragma unroll
    for (int mi = 0; mi < 4; ++mi)
        #pragma unroll
        for (int ni = 0; ni < 4; ++ni) {
            int r0 = by * 128 + wm * 64 + mi * 16 + (lane >> 2);
            int c0 = bx * 128 + wn * 32 + ni * 8 + (lane & 3) * 2;
            #pragma unroll
            for (int half = 0; half < 2; ++half) {
                int gr = r0 + half * 8;
                float v0 = acc[mi][ni][half * 2 + 0];
                float v1 = acc[mi][ni][half * 2 + 1];
                bf16 h0 = __float2bfloat16(v0); bf16 l0 = __float2bfloat16(v0 - __bfloat162float(h0));
                bf16 h1 = __float2bfloat16(v1); bf16 l1 = __float2bfloat16(v1 - __bfloat162float(h1));
                *reinterpret_cast<__nv_bfloat162*>(Oh + (size_t)gr * D_ + c0) = __halves2bfloat162(h0, h1);
                *reinterpret_cast<__nv_bfloat162*>(Ol + (size_t)gr * D_ + c0) = __halves2bfloat162(l0, l1);
            }
        }
}

// ---------------------------------------------------------------------------
// Scores with compact triangular launch: grid.x = 136 live blocks.
// ---------------------------------------------------------------------------
__global__ __launch_bounds__(NTHR, 2)
void tc_scores_kernel()
{
    const int idx = blockIdx.x;
    int by = (int)((sqrtf(8.f * idx + 1.f) - 1.f) * 0.5f);
    while ((by + 1) * (by + 2) / 2 <= idx) ++by;
    while (by * (by + 1) / 2 > idx) --by;
    const int bx = idx - by * (by + 1) / 2;
    const int b = blockIdx.z;

    extern __shared__ char smem[];
    uint32_t sb = smem_u32(smem);

    size_t aoff = ((size_t)b * S_ + by * 128) * D_;
    size_t boff = ((size_t)b * S_ + bx * 128) * D_;
    float acc[4][4][4];
    gemm_run<0>(sb, g_qh + aoff, g_ql + aoff, D_,
                    g_kh + boff, g_kl + boff, D_, D_ / 32, acc);

    const int tid = threadIdx.x, lane = tid & 31, wid = tid >> 5;
    const int wm = wid & 1, wn = wid >> 1;
    const bool diag = (bx == by);
    const float alpha = 0.03125f;
    float* out = g_s + (size_t)b * S_ * S_;

    #pragma unroll
    for (int mi = 0; mi < 4; ++mi)
        #pragma unroll
        for (int ni = 0; ni < 4; ++ni) {
            int r0 = by * 128 + wm * 64 + mi * 16 + (lane >> 2);
            int c0 = bx * 128 + wn * 32 + ni * 8 + (lane & 3) * 2;
            #pragma unroll
            for (int half = 0; half < 2; ++half) {
                int gr = r0 + half * 8;
                float s0 = acc[mi][ni][half * 2 + 0] * alpha;
                float s1 = acc[mi][ni][half * 2 + 1] * alpha;
                if (diag) {
                    if (c0 > gr)     s0 = -CUDART_INF_F;
                    if (c0 + 1 > gr) s1 = -CUDART_INF_F;
                }
                *reinterpret_cast<float2*>(out + (size_t)gr * S_ + c0) = make_float2(s0, s1);
            }
        }
}

// ---------------------------------------------------------------------------
// Softmax over causal prefix; vectorized (float2 in, bf16x2 out h/l split).
// ---------------------------------------------------------------------------
__global__ __launch_bounds__(256)
void softmax_split_kernel()
{
    const int q = blockIdx.x;
    const int b = blockIdx.y;
    const size_t off = (size_t)b * S_ * S_ + (size_t)q * S_;
    const float2* row2 = reinterpret_cast<const float2*>(g_s + off);
    const int L2 = (((q >> 7) + 1) << 7) >> 1;   // pairs, <= 1024
    const int tid = threadIdx.x;

    float2 v[4];
    float m = -CUDART_INF_F;
    #pragma unroll
    for (int j = 0; j < 4; ++j) {
        int i = tid + j * 256;
        if (i < L2) { v[j] = row2[i]; m = fmaxf(m, fmaxf(v[j].x, v[j].y)); }
        else        { v[j] = make_float2(-CUDART_INF_F, -CUDART_INF_F); }
    }
    #pragma unroll
    for (int o = 16; o > 0; o >>= 1) m = fmaxf(m, __shfl_xor_sync(0xFFFFFFFFu, m, o));
    __shared__ float red[8];
    if ((tid & 31) == 0) red[tid >> 5] = m;
    __syncthreads();
    float mg = red[0];
    #pragma unroll
    for (int j = 1; j < 8; ++j) mg = fmaxf(mg, red[j]);
    __syncthreads();

    float sum = 0.f;
    #pragma unroll
    for (int j = 0; j < 4; ++j) {
        int i = tid + j * 256;
        if (i < L2) {
            v[j].x = __expf(v[j].x - mg);
            v[j].y = __expf(v[j].y - mg);
            sum += v[j].x + v[j].y;
        }
    }
    #pragma unroll
    for (int o = 16; o > 0; o >>= 1) sum += __shfl_xor_sync(0xFFFFFFFFu, sum, o);
    if ((tid & 31) == 0) red[tid >> 5] = sum;
    __syncthreads();
    float tot = 0.f;
    #pragma unroll
    for (int j = 0; j < 8; ++j) tot += red[j];
    float inv = 1.0f / tot;

    __nv_bfloat162* ph2 = reinterpret_cast<__nv_bfloat162*>(g_ph + off);
    __nv_bfloat162* pl2 = reinterpret_cast<__nv_bfloat162*>(g_pl + off);
    #pragma unroll
    for (int j = 0; j < 4; ++j) {
        int i = tid + j * 256;
        if (i < L2) {
            float p0 = v[j].x * inv, p1 = v[j].y * inv;
            bf16 h0 = __float2bfloat16(p0); bf16 l0 = __float2bfloat16(p0 - __bfloat162float(h0));
            bf16 h1 = __float2bfloat16(p1); bf16 l1 = __float2bfloat16(p1 - __bfloat162float(h1));
            ph2[i] = __halves2bfloat162(h0, h1);
            pl2[i] = __halves2bfloat162(l0, l1);
        }
    }
}

// ---------------------------------------------------------------------------
// PV with split-K: grid (bx, b, order). Order table gives (by, piece) in
// descending-niter order. piece<0: full tile -> out. piece 0: lower half -> 
// scratch (g_s). piece 1: upper half -> out. Combine kernel adds partials.
// ---------------------------------------------------------------------------
__global__ __launch_bounds__(NTHR, 2)
void tc_pv_kernel(float* __restrict__ out)
{
    const int bx = blockIdx.x;   // d tile
    const int b  = blockIdx.y;
    const int o  = blockIdx.z;
    const int by = d_pv_by[o];
    const int piece = d_pv_piece[o];

    extern __shared__ char smem[];
    uint32_t sb = smem_u32(smem);

    const int total = (by + 1) * 4;
    int niter, k0i;
    if (piece < 0) { niter = total;      k0i = 0; }
    else           { niter = total >> 1; k0i = piece ? niter : 0; }
    const int k0 = k0i * 32;   // k elements

    size_t aoff = (size_t)b * S_ * S_ + (size_t)by * 128 * S_ + k0;
    size_t boff = (size_t)b * S_ * D_ + (size_t)bx * 128 + (size_t)k0 * D_;

    float acc[4][4][4];
    gemm_run<1>(sb, g_ph + aoff, g_pl + aoff, S_,
                    g_vh + boff, g_vl + boff, D_, niter, acc);

    const int tid = threadIdx.x, lane = tid & 31, wid = tid >> 5;
    const int wm = wid & 1, wn = wid >> 1;

    if (piece == 0) {
        // lower-half partial -> scratch tile [128][128] contiguous
        const int sidx = (by - 8) + 8 * (bx + 8 * b);
        float* dst = g_s + (size_t)sidx * 16384;
        #pragma unroll
        for (int mi = 0; mi < 4; ++mi)
            #pragma unroll
            for (int ni = 0; ni < 4; ++ni) {
                int rl = wm * 64 + mi * 16 + (lane >> 2);
                int cl = wn * 32 + ni * 8 + (lane & 3) * 2;
                #pragma unroll
                for (int half = 0; half < 2; ++half)
                    *reinterpret_cast<float2*>(dst + (rl + half * 8) * 128 + cl) =
                        make_float2(acc[mi][ni][half * 2 + 0], acc[mi][ni][half * 2 + 1]);
            }
    } else {
        #pragma unroll
        for (int mi = 0; mi < 4; ++mi)
            #pragma unroll
            for (int ni = 0; ni < 4; ++ni) {
                int r0 = by * 128 + wm * 64 + mi * 16 + (lane >> 2);
                int c0 = bx * 128 + wn * 32 + ni * 8 + (lane & 3) * 2;
                #pragma unroll
                for (int half = 0; half < 2; ++half) {
                    int gq = r0 + half * 8;
                    *reinterpret_cast<float2*>(out + ((size_t)(b * S_ + gq)) * D_ + c0) =
                        make_float2(acc[mi][ni][half * 2 + 0], acc[mi][ni][half * 2 + 1]);
                }
            }
    }
}

// Add the 256 lower-half partials into out. Deterministic (plain adds).
__global__ __launch_bounds__(256)
void pv_combine_kernel(float* __restrict__ out)
{
    const int tile = blockIdx.x;            // == sidx
    const int b  = tile >> 6;
    const int bx = (tile >> 3) & 7;
    const int by = (tile & 7) + 8;
    const float4* src = reinterpret_cast<const float4*>(g_s + (size_t)tile * 16384);
    const int tid = threadIdx.x;

    #pragma unroll
    for (int j = 0; j < 16; ++j) {
        int f4 = j * 256 + tid;             // [0,4096)
        int r  = f4 >> 5;                   // 32 float4 per row
        int c4 = f4 & 31;
        float4 s = src[f4];
        float4* op = reinterpret_cast<float4*>(
            out + ((size_t)(b * S_ + by * 128 + r)) * D_ + bx * 128 + c4 * 4);
        float4 v = *op;
        v.x += s.x; v.y += s.y; v.z += s.z; v.w += s.w;
        *op = v;
    }
}

// ---------------------------------------------------------------------------
extern "C" void kernel_launch(void* const* d_in, const int* in_sizes, int n_in,
                              void* d_out, int out_size)
{
    const float* x  = (const float*)d_in[0];
    const float* wq = (const float*)d_in[1];
    const float* wk = (const float*)d_in[2];
    const float* wv = (const float*)d_in[3];
    float* out = (float*)d_out;

    bf16 *xh, *xl, *wqh, *wql, *wkh, *wkl, *wvh, *wvl;
    cudaGetSymbolAddress((void**)&xh,  g_xh);  cudaGetSymbolAddress((void**)&xl,  g_xl);
    cudaGetSymbolAddress((void**)&wqh, g_wqh); cudaGetSymbolAddress((void**)&wql, g_wql);
    cudaGetSymbolAddress((void**)&wkh, g_wkh); cudaGetSymbolAddress((void**)&wkl, g_wkl);
    cudaGetSymbolAddress((void**)&wvh, g_wvh); cudaGetSymbolAddress((void**)&wvl, g_wvl);

    static bool attr_done = false;
    if (!attr_done) {
        cudaFuncSetAttribute(tc_proj_kernel,   cudaFuncAttributeMaxDynamicSharedMemorySize, SMEM_TOTAL);
        cudaFuncSetAttribute(tc_scores_kernel, cudaFuncAttributeMaxDynamicSharedMemorySize, SMEM_TOTAL);
        cudaFuncSetAttribute(tc_pv_kernel,     cudaFuncAttributeMaxDynamicSharedMemorySize, SMEM_TOTAL);
        attr_done = true;
    }

    // All fp32 -> bf16 hi/lo splits in one launch
    {
        dim3 gs((M_ * D_ / 4 + 255) / 256, 4);
        split_all_kernel<<<gs, 256>>>((const float4*)x, (const float4*)wq,
            (const float4*)wk, (const float4*)wv,
            (__nv_bfloat162*)xh, (__nv_bfloat162*)xl,
            (__nv_bfloat162*)wqh, (__nv_bfloat162*)wql,
            (__nv_bfloat162*)wkh, (__nv_bfloat162*)wkl,
            (__nv_bfloat162*)wvh, (__nv_bfloat162*)wvl);
    }

    // QKV projections in one launch (z selects W/dst)
    dim3 gproj(D_ / 128, M_ / 128, 3);
    tc_proj_kernel<<<gproj, NTHR, SMEM_TOTAL>>>(xh, xl);

    // Scores: compact triangular grid (136 live blocks per batch)
    dim3 gsc(136, 1, B_);
    tc_scores_kernel<<<gsc, NTHR, SMEM_TOTAL>>>();

    // Softmax + P split
    dim3 gsm(S_, B_);
    softmax_split_kernel<<<gsm, 256>>>();

    // P @ V with split-K (descending work order), then combine partials
    dim3 gpv(D_ / 128, B_, 24);
    tc_pv_kernel<<<gpv, NTHR, SMEM_TOTAL>>>(out);
    pv_combine_kernel<<<256, 256>>>(out);
}

// round 11
// speedup vs baseline: 3.4132x; 1.0130x over previous
#include <cuda_runtime.h>
#include <cuda_bf16.h>
#include <cstdint>
#include <math.h>
#include <math_constants.h>

#define B_ 4
#define S_ 2048
#define D_ 1024
#define M_ (B_*S_)   // 8192

typedef __nv_bfloat16 bf16;

// ---------------------------------------------------------------------------
// Scratch (__device__ globals; allocation-free)
// ---------------------------------------------------------------------------
__device__ __align__(256) bf16 g_xh[M_*D_], g_xl[M_*D_];
__device__ __align__(256) bf16 g_wqh[D_*D_], g_wql[D_*D_];
__device__ __align__(256) bf16 g_wkh[D_*D_], g_wkl[D_*D_];
__device__ __align__(256) bf16 g_wvh[D_*D_], g_wvl[D_*D_];
__device__ __align__(256) bf16 g_qh[M_*D_], g_ql[M_*D_];
__device__ __align__(256) bf16 g_kh[M_*D_], g_kl[M_*D_];
__device__ __align__(256) bf16 g_vh[M_*D_], g_vl[M_*D_];      // V natural [b][s][d]
__device__ __align__(256) float g_s[(size_t)B_*S_*S_];        // scores / partial scratch
__device__ __align__(256) bf16 g_ph[(size_t)B_*S_*S_], g_pl[(size_t)B_*S_*S_];

// Proj split-K partial scratch lives in batch-3 scores region (written later).
#define PROJ_SCR ((size_t)3 * S_ * S_)

// PV schedule: 24 entries per (b,bx), descending niter for work-steal packing.
__device__ const int d_pv_by[24]    = {15,15,7,14,14,13,13,6,12,12,11,11,5,10,10,9,9,4,8,8,3,2,1,0};
__device__ const int d_pv_piece[24] = { 0, 1,-1, 0, 1, 0, 1,-1, 0, 1, 0, 1,-1, 0, 1,0,1,-1,0,1,-1,-1,-1,-1};

// ---------------------------------------------------------------------------
#define LDBT_S 136
#define STG 33792u
#define OFF_AH(s) ((s)*STG)
#define OFF_AL(s) ((s)*STG + 8192u)
#define OFF_BH(s) ((s)*STG + 16384u)
#define OFF_BL(s) ((s)*STG + 25088u)
#define SMEM_TOTAL (3*33792)
#define NTHR 256

__device__ __forceinline__ uint32_t swz(int r, int k) {
    return (uint32_t)(r * 64 + ((((k >> 3) ^ ((r >> 1) & 3)) << 4) | ((k & 7) << 1)));
}
__device__ __forceinline__ uint32_t smem_u32(const void* p) {
    uint32_t a;
    asm("{ .reg .u64 t; cvta.to.shared.u64 t, %1; cvt.u32.u64 %0, t; }" : "=r"(a) : "l"(p));
    return a;
}
__device__ __forceinline__ void cpa16(uint32_t s, const void* g) {
    asm volatile("cp.async.cg.shared.global [%0], [%1], 16;" :: "r"(s), "l"(g));
}
__device__ __forceinline__ void ldm_x4(uint32_t addr, uint32_t r[4]) {
    asm volatile("ldmatrix.sync.aligned.m8n8.x4.shared.b16 {%0,%1,%2,%3}, [%4];"
        : "=r"(r[0]), "=r"(r[1]), "=r"(r[2]), "=r"(r[3]) : "r"(addr));
}
__device__ __forceinline__ void ldm_x4_t(uint32_t addr, uint32_t r[4]) {
    asm volatile("ldmatrix.sync.aligned.m8n8.x4.trans.shared.b16 {%0,%1,%2,%3}, [%4];"
        : "=r"(r[0]), "=r"(r[1]), "=r"(r[2]), "=r"(r[3]) : "r"(addr));
}
__device__ __forceinline__ void mma16816(float c[4], const uint32_t a[4], const uint32_t b[2]) {
    asm volatile("mma.sync.aligned.m16n8k16.row.col.f32.bf16.bf16.f32 "
        "{%0,%1,%2,%3}, {%4,%5,%6,%7}, {%8,%9}, {%0,%1,%2,%3};"
        : "+f"(c[0]), "+f"(c[1]), "+f"(c[2]), "+f"(c[3])
        : "r"(a[0]), "r"(a[1]), "r"(a[2]), "r"(a[3]), "r"(b[0]), "r"(b[1]));
}

// ---------------------------------------------------------------------------
template<int BT>
__device__ __forceinline__ void load_stage(uint32_t sb, int st, int tid,
    const bf16* __restrict__ Ah, const bf16* __restrict__ Al, int lda,
    const bf16* __restrict__ Bh, const bf16* __restrict__ Bl, int ldb, int k0)
{
    #pragma unroll
    for (int it = 0; it < 2; ++it) {
        int c = tid + it * NTHR;
        int row = c >> 2;
        int kc  = (c & 3) << 3;
        uint32_t so = swz(row, kc);
        cpa16(sb + OFF_AH(st) + so, Ah + (size_t)row * lda + k0 + kc);
        cpa16(sb + OFF_AL(st) + so, Al + (size_t)row * lda + k0 + kc);
        if (BT == 0) {
            cpa16(sb + OFF_BH(st) + so, Bh + (size_t)row * ldb + k0 + kc);
            cpa16(sb + OFF_BL(st) + so, Bl + (size_t)row * ldb + k0 + kc);
        } else {
            int br = c >> 4;
            int bn = (c & 15) << 3;
            uint32_t bo = (uint32_t)((br * LDBT_S + bn) * 2);
            cpa16(sb + OFF_BH(st) + bo, Bh + (size_t)(k0 + br) * ldb + bn);
            cpa16(sb + OFF_BL(st) + bo, Bl + (size_t)(k0 + br) * ldb + bn);
        }
    }
}

template<int BT>
__device__ __forceinline__ void compute_stage(uint32_t sb, int st, int lane,
                                              int wm, int wn, float acc[4][4][4])
{
    const uint32_t sAh = sb + OFF_AH(st);
    const uint32_t sAl = sb + OFF_AL(st);
    const uint32_t sBh = sb + OFF_BH(st);
    const uint32_t sBl = sb + OFF_BL(st);

    #pragma unroll
    for (int ks = 0; ks < 2; ++ks) {
        uint32_t bh[4][2], bl[4][2];
        if (BT == 0) {
            int nr = (lane & 7) + ((lane >> 4) & 1) * 8;
            int kh = ks * 16 + ((lane >> 3) & 1) * 8;
            #pragma unroll
            for (int np = 0; np < 2; ++np) {
                uint32_t off = swz(wn * 32 + np * 16 + nr, kh);
                uint32_t r[4];
                ldm_x4(sBh + off, r);
                bh[2*np][0] = r[0]; bh[2*np][1] = r[1];
                bh[2*np+1][0] = r[2]; bh[2*np+1][1] = r[3];
                ldm_x4(sBl + off, r);
                bl[2*np][0] = r[0]; bl[2*np][1] = r[1];
                bl[2*np+1][0] = r[2]; bl[2*np+1][1] = r[3];
            }
        } else {
            int kr = ks * 16 + ((lane >> 3) & 1) * 8 + (lane & 7);
            int nh = ((lane >> 4) & 1) * 8;
            #pragma unroll
            for (int np = 0; np < 2; ++np) {
                uint32_t off = (uint32_t)((kr * LDBT_S + wn * 32 + np * 16 + nh) * 2);
                uint32_t r[4];
                ldm_x4_t(sBh + off, r);
                bh[2*np][0] = r[0]; bh[2*np][1] = r[1];
                bh[2*np+1][0] = r[2]; bh[2*np+1][1] = r[3];
                ldm_x4_t(sBl + off, r);
                bl[2*np][0] = r[0]; bl[2*np][1] = r[1];
                bl[2*np+1][0] = r[2]; bl[2*np+1][1] = r[3];
            }
        }

        const int arow = wm * 64 + (lane & 15);
        const int akh  = ks * 16 + (lane >> 4) * 8;
        #pragma unroll
        for (int mi = 0; mi < 4; ++mi) {
            uint32_t ah[4], al[4];
            uint32_t off = swz(arow + mi * 16, akh);
            ldm_x4(sAh + off, ah);
            ldm_x4(sAl + off, al);
            #pragma unroll
            for (int ni = 0; ni < 4; ++ni) {
                mma16816(acc[mi][ni], ah, bh[ni]);
                mma16816(acc[mi][ni], ah, bl[ni]);
                mma16816(acc[mi][ni], al, bh[ni]);
            }
        }
    }
}

// 3-stage pipelined mainloop; one __syncthreads per iteration. niter >= 2.
template<int BT>
__device__ __forceinline__ void gemm_run(uint32_t sb,
    const bf16* __restrict__ Ah, const bf16* __restrict__ Al, int lda,
    const bf16* __restrict__ Bh, const bf16* __restrict__ Bl, int ldb,
    int niter, float acc[4][4][4])
{
    const int tid = threadIdx.x;
    const int lane = tid & 31, wid = tid >> 5;
    const int wm = wid & 1, wn = wid >> 1;

    #pragma unroll
    for (int mi = 0; mi < 4; ++mi)
        #pragma unroll
        for (int ni = 0; ni < 4; ++ni)
            #pragma unroll
            for (int j = 0; j < 4; ++j) acc[mi][ni][j] = 0.f;

    load_stage<BT>(sb, 0, tid, Ah, Al, lda, Bh, Bl, ldb, 0);
    asm volatile("cp.async.commit_group;" ::: "memory");
    load_stage<BT>(sb, 1, tid, Ah, Al, lda, Bh, Bl, ldb, 32);
    asm volatile("cp.async.commit_group;" ::: "memory");

    int st = 0;
    for (int i = 0; i < niter; ++i) {
        if (i + 1 < niter) asm volatile("cp.async.wait_group 1;" ::: "memory");
        else               asm volatile("cp.async.wait_group 0;" ::: "memory");
        __syncthreads();
        if (i + 2 < niter) {
            int slot = st + 2 >= 3 ? st - 1 : st + 2;
            load_stage<BT>(sb, slot, tid, Ah, Al, lda, Bh, Bl, ldb, (i + 2) * 32);
            asm volatile("cp.async.commit_group;" ::: "memory");
        }
        compute_stage<BT>(sb, st, lane, wm, wn, acc);
        st = (st == 2) ? 0 : st + 1;
    }
}

// ---------------------------------------------------------------------------
// Merged split: fp32 -> bf16 hi/lo for all 4 tensors in one launch.
// ---------------------------------------------------------------------------
__global__ __launch_bounds__(256)
void split_all_kernel(const float4* __restrict__ x,  const float4* __restrict__ wq,
                      const float4* __restrict__ wk, const float4* __restrict__ wv,
                      __nv_bfloat162* __restrict__ xh,  __nv_bfloat162* __restrict__ xl,
                      __nv_bfloat162* __restrict__ wqh, __nv_bfloat162* __restrict__ wql,
                      __nv_bfloat162* __restrict__ wkh, __nv_bfloat162* __restrict__ wkl,
                      __nv_bfloat162* __restrict__ wvh, __nv_bfloat162* __restrict__ wvl)
{
    const int t = blockIdx.y;
    const float4* in; __nv_bfloat162 *hi, *lo; int n4;
    if (t == 0)      { in = x;  hi = xh;  lo = xl;  n4 = M_*D_/4; }
    else if (t == 1) { in = wq; hi = wqh; lo = wql; n4 = D_*D_/4; }
    else if (t == 2) { in = wk; hi = wkh; lo = wkl; n4 = D_*D_/4; }
    else             { in = wv; hi = wvh; lo = wvl; n4 = D_*D_/4; }

    int i = blockIdx.x * 256 + threadIdx.x;
    if (i >= n4) return;
    float4 v = in[i];
    bf16 h0 = __float2bfloat16(v.x); bf16 l0 = __float2bfloat16(v.x - __bfloat162float(h0));
    bf16 h1 = __float2bfloat16(v.y); bf16 l1 = __float2bfloat16(v.y - __bfloat162float(h1));
    bf16 h2 = __float2bfloat16(v.z); bf16 l2 = __float2bfloat16(v.z - __bfloat162float(h2));
    bf16 h3 = __float2bfloat16(v.w); bf16 l3 = __float2bfloat16(v.w - __bfloat162float(h3));
    hi[2*i]   = __halves2bfloat162(h0, h1);
    hi[2*i+1] = __halves2bfloat162(h2, h3);
    lo[2*i]   = __halves2bfloat162(l0, l1);
    lo[2*i+1] = __halves2bfloat162(l2, l3);
}

// ---------------------------------------------------------------------------
// Projection, 1D grid of 1552 blocks.
// id < 1520: full tile (32 k-iters). id >= 1520: k-half piece of the last 16
// tiles (z=2, by 62..63), fp32 partial -> scratch. Halves dispatch last,
// filling the straggler wave exactly.
// ---------------------------------------------------------------------------
__global__ __launch_bounds__(NTHR, 2)
void tc_proj_kernel(const bf16* __restrict__ Ah, const bf16* __restrict__ Al)
{
    extern __shared__ char smem[];
    uint32_t sb = smem_u32(smem);
    const int id = blockIdx.x;

    int tile, niter, k0e, piece;
    if (id < 1520) { tile = id; niter = 32; k0e = 0; piece = -1; }
    else { int p = id - 1520; tile = 1520 + (p >> 1); niter = 16; k0e = (p & 1) * 512; piece = p; }
    const int z = tile >> 9, by = (tile >> 3) & 63, bx = tile & 7;

    const bf16 *Bh, *Bl;
    bf16 *Oh, *Ol;
    if (z == 0)      { Bh = g_wqh; Bl = g_wql; Oh = g_qh; Ol = g_ql; }
    else if (z == 1) { Bh = g_wkh; Bl = g_wkl; Oh = g_kh; Ol = g_kl; }
    else             { Bh = g_wvh; Bl = g_wvl; Oh = g_vh; Ol = g_vl; }

    float acc[4][4][4];
    gemm_run<0>(sb,
        Ah + (size_t)by * 128 * D_ + k0e, Al + (size_t)by * 128 * D_ + k0e, D_,
        Bh + (size_t)bx * 128 * D_ + k0e, Bl + (size_t)bx * 128 * D_ + k0e, D_,
        niter, acc);

    const int tid = threadIdx.x, lane = tid & 31, wid = tid >> 5;
    const int wm = wid & 1, wn = wid >> 1;

    if (piece < 0) {
        #pragma unroll
        for (int mi = 0; mi < 4; ++mi)
            #pragma unroll
            for (int ni = 0; ni < 4; ++ni) {
                int r0 = by * 128 + wm * 64 + mi * 16 + (lane >> 2);
                int c0 = bx * 128 + wn * 32 + ni * 8 + (lane & 3) * 2;
                #pragma unroll
                for (int half = 0; half < 2; ++half) {
                    int gr = r0 + half * 8;
                    float v0 = acc[mi][ni][half * 2 + 0];
                    float v1 = acc[mi][ni][half * 2 + 1];
                    bf16 h0 = __float2bfloat16(v0); bf16 l0 = __float2bfloat16(v0 - __bfloat162float(h0));
                    bf16 h1 = __float2bfloat16(v1); bf16 l1 = __float2bfloat16(v1 - __bfloat162float(h1));
                    *reinterpret_cast<__nv_bfloat162*>(Oh + (size_t)gr * D_ + c0) = __halves2bfloat162(h0, h1);
                    *reinterpret_cast<__nv_bfloat162*>(Ol + (size_t)gr * D_ + c0) = __halves2bfloat162(l0, l1);
                }
            }
    } else {
        float* dst = g_s + PROJ_SCR + (size_t)piece * 16384;
        #pragma unroll
        for (int mi = 0; mi < 4; ++mi)
            #pragma unroll
            for (int ni = 0; ni < 4; ++ni) {
                int rl = wm * 64 + mi * 16 + (lane >> 2);
                int cl = wn * 32 + ni * 8 + (lane & 3) * 2;
                #pragma unroll
                for (int half = 0; half < 2; ++half)
                    *reinterpret_cast<float2*>(dst + (rl + half * 8) * 128 + cl) =
                        make_float2(acc[mi][ni][half * 2 + 0], acc[mi][ni][half * 2 + 1]);
            }
    }
}

// Combine the 32 proj half-partials into V hi/lo (16 tiles, z=2, by 62..63).
__global__ __launch_bounds__(256)
void proj_tail_combine_kernel()
{
    const int t = blockIdx.x;              // [0,16)
    const int tile = 1520 + t;
    const int by = (tile >> 3) & 63, bx = tile & 7;
    const float4* p0 = reinterpret_cast<const float4*>(g_s + PROJ_SCR + (size_t)(2*t)   * 16384);
    const float4* p1 = reinterpret_cast<const float4*>(g_s + PROJ_SCR + (size_t)(2*t+1) * 16384);
    const int tid = threadIdx.x;

    #pragma unroll
    for (int j = 0; j < 16; ++j) {
        int f4 = j * 256 + tid;            // [0,4096)
        int r  = f4 >> 5;
        int c4 = f4 & 31;
        float4 a = p0[f4], b = p1[f4];
        float v[4] = {a.x + b.x, a.y + b.y, a.z + b.z, a.w + b.w};
        size_t base = (size_t)(by * 128 + r) * D_ + bx * 128 + c4 * 4;
        #pragma unroll
        for (int e = 0; e < 4; e += 2) {
            bf16 h0 = __float2bfloat16(v[e]);   bf16 l0 = __float2bfloat16(v[e]   - __bfloat162float(h0));
            bf16 h1 = __float2bfloat16(v[e+1]); bf16 l1 = __float2bfloat16(v[e+1] - __bfloat162float(h1));
            *reinterpret_cast<__nv_bfloat162*>(g_vh + base + e) = __halves2bfloat162(h0, h1);
            *reinterpret_cast<__nv_bfloat162*>(g_vl + base + e) = __halves2bfloat162(l0, l1);
        }
    }
}

// ---------------------------------------------------------------------------
// Scores (all batches): compact triangular grid of 136 blocks x B.
// ---------------------------------------------------------------------------
__global__ __launch_bounds__(NTHR, 2)
void tc_scores_kernel()
{
    const int idx = blockIdx.x;
    int by = (int)((sqrtf(8.f * idx + 1.f) - 1.f) * 0.5f);
    while ((by + 1) * (by + 2) / 2 <= idx) ++by;
    while (by * (by + 1) / 2 > idx) --by;
    const int bx = idx - by * (by + 1) / 2;
    const int b = blockIdx.z;

    extern __shared__ char smem[];
    uint32_t sb = smem_u32(smem);

    size_t aoff = ((size_t)b * S_ + by * 128) * D_;
    size_t boff = ((size_t)b * S_ + bx * 128) * D_;
    float acc[4][4][4];
    gemm_run<0>(sb, g_qh + aoff, g_ql + aoff, D_,
                    g_kh + boff, g_kl + boff, D_, D_ / 32, acc);

    const int tid = threadIdx.x, lane = tid & 31, wid = tid >> 5;
    const int wm = wid & 1, wn = wid >> 1;
    const bool diag = (bx == by);
    const float alpha = 0.03125f;
    float* out = g_s + (size_t)b * S_ * S_;

    #pragma unroll
    for (int mi = 0; mi < 4; ++mi)
        #pragma unroll
        for (int ni = 0; ni < 4; ++ni) {
            int r0 = by * 128 + wm * 64 + mi * 16 + (lane >> 2);
            int c0 = bx * 128 + wn * 32 + ni * 8 + (lane & 3) * 2;
            #pragma unroll
            for (int half = 0; half < 2; ++half) {
                int gr = r0 + half * 8;
                float s0 = acc[mi][ni][half * 2 + 0] * alpha;
                float s1 = acc[mi][ni][half * 2 + 1] * alpha;
                if (diag) {
                    if (c0 > gr)     s0 = -CUDART_INF_F;
                    if (c0 + 1 > gr) s1 = -CUDART_INF_F;
                }
                *reinterpret_cast<float2*>(out + (size_t)gr * S_ + c0) = make_float2(s0, s1);
            }
        }
}

// ---------------------------------------------------------------------------
// Softmax over causal prefix; float2 in, bf16x2 h/l out.
// ---------------------------------------------------------------------------
__global__ __launch_bounds__(256)
void softmax_split_kernel()
{
    const int q = blockIdx.x;
    const int b = blockIdx.y;
    const size_t off = (size_t)b * S_ * S_ + (size_t)q * S_;
    const float2* row2 = reinterpret_cast<const float2*>(g_s + off);
    const int L2 = (((q >> 7) + 1) << 7) >> 1;
    const int tid = threadIdx.x;

    float2 v[4];
    float m = -CUDART_INF_F;
    #pragma unroll
    for (int j = 0; j < 4; ++j) {
        int i = tid + j * 256;
        if (i < L2) { v[j] = row2[i]; m = fmaxf(m, fmaxf(v[j].x, v[j].y)); }
        else        { v[j] = make_float2(-CUDART_INF_F, -CUDART_INF_F); }
    }
    #pragma unroll
    for (int o = 16; o > 0; o >>= 1) m = fmaxf(m, __shfl_xor_sync(0xFFFFFFFFu, m, o));
    __shared__ float red[8];
    if ((tid & 31) == 0) red[tid >> 5] = m;
    __syncthreads();
    float mg = red[0];
    #pragma unroll
    for (int j = 1; j < 8; ++j) mg = fmaxf(mg, red[j]);
    __syncthreads();

    float sum = 0.f;
    #pragma unroll
    for (int j = 0; j < 4; ++j) {
        int i = tid + j * 256;
        if (i < L2) {
            v[j].x = __expf(v[j].x - mg);
            v[j].y = __expf(v[j].y - mg);
            sum += v[j].x + v[j].y;
        }
    }
    #pragma unroll
    for (int o = 16; o > 0; o >>= 1) sum += __shfl_xor_sync(0xFFFFFFFFu, sum, o);
    if ((tid & 31) == 0) red[tid >> 5] = sum;
    __syncthreads();
    float tot = 0.f;
    #pragma unroll
    for (int j = 0; j < 8; ++j) tot += red[j];
    float inv = 1.0f / tot;

    __nv_bfloat162* ph2 = reinterpret_cast<__nv_bfloat162*>(g_ph + off);
    __nv_bfloat162* pl2 = reinterpret_cast<__nv_bfloat162*>(g_pl + off);
    #pragma unroll
    for (int j = 0; j < 4; ++j) {
        int i = tid + j * 256;
        if (i < L2) {
            float p0 = v[j].x * inv, p1 = v[j].y * inv;
            bf16 h0 = __float2bfloat16(p0); bf16 l0 = __float2bfloat16(p0 - __bfloat162float(h0));
            bf16 h1 = __float2bfloat16(p1); bf16 l1 = __float2bfloat16(p1 - __bfloat162float(h1));
            ph2[i] = __halves2bfloat162(h0, h1);
            pl2[i] = __halves2bfloat162(l0, l1);
        }
    }
}

// ---------------------------------------------------------------------------
// PV (all batches) with split-K; grid (8 bx, B, 24 order).
// ---------------------------------------------------------------------------
__global__ __launch_bounds__(NTHR, 2)
void tc_pv_kernel(float* __restrict__ out)
{
    const int bx = blockIdx.x;
    const int b  = blockIdx.y;
    const int o  = blockIdx.z;
    const int by = d_pv_by[o];
    const int piece = d_pv_piece[o];

    extern __shared__ char smem[];
    uint32_t sb = smem_u32(smem);

    const int total = (by + 1) * 4;
    int niter, k0i;
    if (piece < 0) { niter = total;      k0i = 0; }
    else           { niter = total >> 1; k0i = piece ? niter : 0; }
    const int k0 = k0i * 32;

    size_t aoff = (size_t)b * S_ * S_ + (size_t)by * 128 * S_ + k0;
    size_t boff = (size_t)b * S_ * D_ + (size_t)bx * 128 + (size_t)k0 * D_;

    float acc[4][4][4];
    gemm_run<1>(sb, g_ph + aoff, g_pl + aoff, S_,
                    g_vh + boff, g_vl + boff, D_, niter, acc);

    const int tid = threadIdx.x, lane = tid & 31, wid = tid >> 5;
    const int wm = wid & 1, wn = wid >> 1;

    if (piece == 0) {
        const int sidx = (by - 8) + 8 * (bx + 8 * b);
        float* dst = g_s + (size_t)sidx * 16384;
        #pragma unroll
        for (int mi = 0; mi < 4; ++mi)
            #pragma unroll
            for (int ni = 0; ni < 4; ++ni) {
                int rl = wm * 64 + mi * 16 + (lane >> 2);
                int cl = wn * 32 + ni * 8 + (lane & 3) * 2;
                #pragma unroll
                for (int half = 0; half < 2; ++half)
                    *reinterpret_cast<float2*>(dst + (rl + half * 8) * 128 + cl) =
                        make_float2(acc[mi][ni][half * 2 + 0], acc[mi][ni][half * 2 + 1]);
            }
    } else {
        #pragma unroll
        for (int mi = 0; mi < 4; ++mi)
            #pragma unroll
            for (int ni = 0; ni < 4; ++ni) {
                int r0 = by * 128 + wm * 64 + mi * 16 + (lane >> 2);
                int c0 = bx * 128 + wn * 32 + ni * 8 + (lane & 3) * 2;
                #pragma unroll
                for (int half = 0; half < 2; ++half) {
                    int gq = r0 + half * 8;
                    *reinterpret_cast<float2*>(out + ((size_t)(b * S_ + gq)) * D_ + c0) =
                        make_float2(acc[mi][ni][half * 2 + 0], acc[mi][ni][half * 2 + 1]);
                }
            }
    }
}

// Add the 256 lower-half partials into out. Deterministic (plain adds).
__global__ __launch_bounds__(256)
void pv_combine_kernel(float* __restrict__ out)
{
    const int tile = blockIdx.x;            // == sidx
    const int b  = tile >> 6;
    const int bx = (tile >> 3) & 7;
    const int by = (tile & 7) + 8;
    const float4* src = reinterpret_cast<const float4*>(g_s + (size_t)tile * 16384);
    const int tid = threadIdx.x;

    #pragma unroll
    for (int j = 0; j < 16; ++j) {
        int f4 = j * 256 + tid;
        int r  = f4 >> 5;
        int c4 = f4 & 31;
        float4 s = src[f4];
        float4* op = reinterpret_cast<float4*>(
            out + ((size_t)(b * S_ + by * 128 + r)) * D_ + bx * 128 + c4 * 4);
        float4 v = *op;
        v.x += s.x; v.y += s.y; v.z += s.z; v.w += s.w;
        *op = v;
    }
}

// ---------------------------------------------------------------------------
extern "C" void kernel_launch(void* const* d_in, const int* in_sizes, int n_in,
                              void* d_out, int out_size)
{
    const float* x  = (const float*)d_in[0];
    const float* wq = (const float*)d_in[1];
    const float* wk = (const float*)d_in[2];
    const float* wv = (const float*)d_in[3];
    float* out = (float*)d_out;

    bf16 *xh, *xl, *wqh, *wql, *wkh, *wkl, *wvh, *wvl;
    cudaGetSymbolAddress((void**)&xh,  g_xh);  cudaGetSymbolAddress((void**)&xl,  g_xl);
    cudaGetSymbolAddress((void**)&wqh, g_wqh); cudaGetSymbolAddress((void**)&wql, g_wql);
    cudaGetSymbolAddress((void**)&wkh, g_wkh); cudaGetSymbolAddress((void**)&wkl, g_wkl);
    cudaGetSymbolAddress((void**)&wvh, g_wvh); cudaGetSymbolAddress((void**)&wvl, g_wvl);

    static bool attr_done = false;
    if (!attr_done) {
        cudaFuncSetAttribute(tc_proj_kernel,   cudaFuncAttributeMaxDynamicSharedMemorySize, SMEM_TOTAL);
        cudaFuncSetAttribute(tc_scores_kernel, cudaFuncAttributeMaxDynamicSharedMemorySize, SMEM_TOTAL);
        cudaFuncSetAttribute(tc_pv_kernel,     cudaFuncAttributeMaxDynamicSharedMemorySize, SMEM_TOTAL);
        attr_done = true;
    }

    // Splits (one launch)
    {
        dim3 gs((M_ * D_ / 4 + 255) / 256, 4);
        split_all_kernel<<<gs, 256>>>((const float4*)x, (const float4*)wq,
            (const float4*)wk, (const float4*)wv,
            (__nv_bfloat162*)xh, (__nv_bfloat162*)xl,
            (__nv_bfloat162*)wqh, (__nv_bfloat162*)wql,
            (__nv_bfloat162*)wkh, (__nv_bfloat162*)wkl,
            (__nv_bfloat162*)wvh, (__nv_bfloat162*)wvl);
    }

    // QKV projections (1520 full + 32 tail halves), then tail combine
    tc_proj_kernel<<<1552, NTHR, SMEM_TOTAL>>>(xh, xl);
    proj_tail_combine_kernel<<<16, 256>>>();

    // Scores: compact triangular grid (136 live blocks per batch)
    dim3 gsc(136, 1, B_);
    tc_scores_kernel<<<gsc, NTHR, SMEM_TOTAL>>>();

    // Softmax + P split
    dim3 gsm(S_, B_);
    softmax_split_kernel<<<gsm, 256>>>();

    // P @ V with split-K (descending work order), then combine partials
    dim3 gpv(D_ / 128, B_, 24);
    tc_pv_kernel<<<gpv, NTHR, SMEM_TOTAL>>>(out);
    pv_combine_kernel<<<256, 256>>>(out);
}

// round 12
// speedup vs baseline: 3.4745x; 1.0180x over previous
#include <cuda_runtime.h>
#include <cuda_bf16.h>
#include <cstdint>
#include <math.h>
#include <math_constants.h>

#define B_ 4
#define S_ 2048
#define D_ 1024
#define M_ (B_*S_)   // 8192

typedef __nv_bfloat16 bf16;

// ---------------------------------------------------------------------------
// Scratch (__device__ globals; allocation-free)
// ---------------------------------------------------------------------------
__device__ __align__(256) bf16 g_xh[M_*D_], g_xl[M_*D_];
__device__ __align__(256) bf16 g_wqh[D_*D_], g_wql[D_*D_];
__device__ __align__(256) bf16 g_wkh[D_*D_], g_wkl[D_*D_];
__device__ __align__(256) bf16 g_wvh[D_*D_], g_wvl[D_*D_];
__device__ __align__(256) bf16 g_qh[M_*D_], g_ql[M_*D_];
__device__ __align__(256) bf16 g_kh[M_*D_], g_kl[M_*D_];
__device__ __align__(256) bf16 g_vh[M_*D_], g_vl[M_*D_];      // V natural [b][s][d]
__device__ __align__(256) float g_s[(size_t)B_*S_*S_];        // scores; then PV split-K partials
__device__ __align__(256) bf16 g_ph[(size_t)B_*S_*S_], g_pl[(size_t)B_*S_*S_];
// Proj split-K fp32 partials live in g_ph (dead until softmax writes it).

// PV schedule: 24 entries per (b,bx), descending niter for work-steal packing.
__device__ const int d_pv_by[24]    = {15,15,7,14,14,13,13,6,12,12,11,11,5,10,10,9,9,4,8,8,3,2,1,0};
__device__ const int d_pv_piece[24] = { 0, 1,-1, 0, 1, 0, 1,-1, 0, 1, 0, 1,-1, 0, 1,0,1,-1,0,1,-1,-1,-1,-1};

// ---------------------------------------------------------------------------
#define LDBT_S 136
#define STG 33792u
#define OFF_AH(s) ((s)*STG)
#define OFF_AL(s) ((s)*STG + 8192u)
#define OFF_BH(s) ((s)*STG + 16384u)
#define OFF_BL(s) ((s)*STG + 25088u)
#define SMEM_TOTAL (3*33792)
#define NTHR 256

__device__ __forceinline__ uint32_t swz(int r, int k) {
    return (uint32_t)(r * 64 + ((((k >> 3) ^ ((r >> 1) & 3)) << 4) | ((k & 7) << 1)));
}
__device__ __forceinline__ uint32_t smem_u32(const void* p) {
    uint32_t a;
    asm("{ .reg .u64 t; cvta.to.shared.u64 t, %1; cvt.u32.u64 %0, t; }" : "=r"(a) : "l"(p));
    return a;
}
__device__ __forceinline__ void cpa16(uint32_t s, const void* g) {
    asm volatile("cp.async.cg.shared.global [%0], [%1], 16;" :: "r"(s), "l"(g));
}
__device__ __forceinline__ void ldm_x4(uint32_t addr, uint32_t r[4]) {
    asm volatile("ldmatrix.sync.aligned.m8n8.x4.shared.b16 {%0,%1,%2,%3}, [%4];"
        : "=r"(r[0]), "=r"(r[1]), "=r"(r[2]), "=r"(r[3]) : "r"(addr));
}
__device__ __forceinline__ void ldm_x4_t(uint32_t addr, uint32_t r[4]) {
    asm volatile("ldmatrix.sync.aligned.m8n8.x4.trans.shared.b16 {%0,%1,%2,%3}, [%4];"
        : "=r"(r[0]), "=r"(r[1]), "=r"(r[2]), "=r"(r[3]) : "r"(addr));
}
__device__ __forceinline__ void mma16816(float c[4], const uint32_t a[4], const uint32_t b[2]) {
    asm volatile("mma.sync.aligned.m16n8k16.row.col.f32.bf16.bf16.f32 "
        "{%0,%1,%2,%3}, {%4,%5,%6,%7}, {%8,%9}, {%0,%1,%2,%3};"
        : "+f"(c[0]), "+f"(c[1]), "+f"(c[2]), "+f"(c[3])
        : "r"(a[0]), "r"(a[1]), "r"(a[2]), "r"(a[3]), "r"(b[0]), "r"(b[1]));
}

// ---------------------------------------------------------------------------
template<int BT>
__device__ __forceinline__ void load_stage(uint32_t sb, int st, int tid,
    const bf16* __restrict__ Ah, const bf16* __restrict__ Al, int lda,
    const bf16* __restrict__ Bh, const bf16* __restrict__ Bl, int ldb, int k0)
{
    #pragma unroll
    for (int it = 0; it < 2; ++it) {
        int c = tid + it * NTHR;
        int row = c >> 2;
        int kc  = (c & 3) << 3;
        uint32_t so = swz(row, kc);
        cpa16(sb + OFF_AH(st) + so, Ah + (size_t)row * lda + k0 + kc);
        cpa16(sb + OFF_AL(st) + so, Al + (size_t)row * lda + k0 + kc);
        if (BT == 0) {
            cpa16(sb + OFF_BH(st) + so, Bh + (size_t)row * ldb + k0 + kc);
            cpa16(sb + OFF_BL(st) + so, Bl + (size_t)row * ldb + k0 + kc);
        } else {
            int br = c >> 4;
            int bn = (c & 15) << 3;
            uint32_t bo = (uint32_t)((br * LDBT_S + bn) * 2);
            cpa16(sb + OFF_BH(st) + bo, Bh + (size_t)(k0 + br) * ldb + bn);
            cpa16(sb + OFF_BL(st) + bo, Bl + (size_t)(k0 + br) * ldb + bn);
        }
    }
}

template<int BT>
__device__ __forceinline__ void compute_stage(uint32_t sb, int st, int lane,
                                              int wm, int wn, float acc[4][4][4])
{
    const uint32_t sAh = sb + OFF_AH(st);
    const uint32_t sAl = sb + OFF_AL(st);
    const uint32_t sBh = sb + OFF_BH(st);
    const uint32_t sBl = sb + OFF_BL(st);

    #pragma unroll
    for (int ks = 0; ks < 2; ++ks) {
        uint32_t bh[4][2], bl[4][2];
        if (BT == 0) {
            int nr = (lane & 7) + ((lane >> 4) & 1) * 8;
            int kh = ks * 16 + ((lane >> 3) & 1) * 8;
            #pragma unroll
            for (int np = 0; np < 2; ++np) {
                uint32_t off = swz(wn * 32 + np * 16 + nr, kh);
                uint32_t r[4];
                ldm_x4(sBh + off, r);
                bh[2*np][0] = r[0]; bh[2*np][1] = r[1];
                bh[2*np+1][0] = r[2]; bh[2*np+1][1] = r[3];
                ldm_x4(sBl + off, r);
                bl[2*np][0] = r[0]; bl[2*np][1] = r[1];
                bl[2*np+1][0] = r[2]; bl[2*np+1][1] = r[3];
            }
        } else {
            int kr = ks * 16 + ((lane >> 3) & 1) * 8 + (lane & 7);
            int nh = ((lane >> 4) & 1) * 8;
            #pragma unroll
            for (int np = 0; np < 2; ++np) {
                uint32_t off = (uint32_t)((kr * LDBT_S + wn * 32 + np * 16 + nh) * 2);
                uint32_t r[4];
                ldm_x4_t(sBh + off, r);
                bh[2*np][0] = r[0]; bh[2*np][1] = r[1];
                bh[2*np+1][0] = r[2]; bh[2*np+1][1] = r[3];
                ldm_x4_t(sBl + off, r);
                bl[2*np][0] = r[0]; bl[2*np][1] = r[1];
                bl[2*np+1][0] = r[2]; bl[2*np+1][1] = r[3];
            }
        }

        const int arow = wm * 64 + (lane & 15);
        const int akh  = ks * 16 + (lane >> 4) * 8;
        #pragma unroll
        for (int mi = 0; mi < 4; ++mi) {
            uint32_t ah[4], al[4];
            uint32_t off = swz(arow + mi * 16, akh);
            ldm_x4(sAh + off, ah);
            ldm_x4(sAl + off, al);
            #pragma unroll
            for (int ni = 0; ni < 4; ++ni) {
                mma16816(acc[mi][ni], ah, bh[ni]);
                mma16816(acc[mi][ni], ah, bl[ni]);
                mma16816(acc[mi][ni], al, bh[ni]);
            }
        }
    }
}

// 3-stage pipelined mainloop; one __syncthreads per iteration. niter >= 2.
template<int BT>
__device__ __forceinline__ void gemm_run(uint32_t sb,
    const bf16* __restrict__ Ah, const bf16* __restrict__ Al, int lda,
    const bf16* __restrict__ Bh, const bf16* __restrict__ Bl, int ldb,
    int niter, float acc[4][4][4])
{
    const int tid = threadIdx.x;
    const int lane = tid & 31, wid = tid >> 5;
    const int wm = wid & 1, wn = wid >> 1;

    #pragma unroll
    for (int mi = 0; mi < 4; ++mi)
        #pragma unroll
        for (int ni = 0; ni < 4; ++ni)
            #pragma unroll
            for (int j = 0; j < 4; ++j) acc[mi][ni][j] = 0.f;

    load_stage<BT>(sb, 0, tid, Ah, Al, lda, Bh, Bl, ldb, 0);
    asm volatile("cp.async.commit_group;" ::: "memory");
    load_stage<BT>(sb, 1, tid, Ah, Al, lda, Bh, Bl, ldb, 32);
    asm volatile("cp.async.commit_group;" ::: "memory");

    int st = 0;
    for (int i = 0; i < niter; ++i) {
        if (i + 1 < niter) asm volatile("cp.async.wait_group 1;" ::: "memory");
        else               asm volatile("cp.async.wait_group 0;" ::: "memory");
        __syncthreads();
        if (i + 2 < niter) {
            int slot = st + 2 >= 3 ? st - 1 : st + 2;
            load_stage<BT>(sb, slot, tid, Ah, Al, lda, Bh, Bl, ldb, (i + 2) * 32);
            asm volatile("cp.async.commit_group;" ::: "memory");
        }
        compute_stage<BT>(sb, st, lane, wm, wn, acc);
        st = (st == 2) ? 0 : st + 1;
    }
}

// Shared epilogue helpers ----------------------------------------------------
__device__ __forceinline__ void epi_bf16_split(float acc[4][4][4], int by, int bx,
                                               bf16* Oh, bf16* Ol)
{
    const int tid = threadIdx.x, lane = tid & 31, wid = tid >> 5;
    const int wm = wid & 1, wn = wid >> 1;
    #pragma unroll
    for (int mi = 0; mi < 4; ++mi)
        #pragma unroll
        for (int ni = 0; ni < 4; ++ni) {
            int r0 = by * 128 + wm * 64 + mi * 16 + (lane >> 2);
            int c0 = bx * 128 + wn * 32 + ni * 8 + (lane & 3) * 2;
            #pragma unroll
            for (int half = 0; half < 2; ++half) {
                int gr = r0 + half * 8;
                float v0 = acc[mi][ni][half * 2 + 0];
                float v1 = acc[mi][ni][half * 2 + 1];
                bf16 h0 = __float2bfloat16(v0); bf16 l0 = __float2bfloat16(v0 - __bfloat162float(h0));
                bf16 h1 = __float2bfloat16(v1); bf16 l1 = __float2bfloat16(v1 - __bfloat162float(h1));
                *reinterpret_cast<__nv_bfloat162*>(Oh + (size_t)gr * D_ + c0) = __halves2bfloat162(h0, h1);
                *reinterpret_cast<__nv_bfloat162*>(Ol + (size_t)gr * D_ + c0) = __halves2bfloat162(l0, l1);
            }
        }
}

__device__ __forceinline__ void epi_f32_tile(float acc[4][4][4], float* dst)
{
    const int tid = threadIdx.x, lane = tid & 31, wid = tid >> 5;
    const int wm = wid & 1, wn = wid >> 1;
    #pragma unroll
    for (int mi = 0; mi < 4; ++mi)
        #pragma unroll
        for (int ni = 0; ni < 4; ++ni) {
            int rl = wm * 64 + mi * 16 + (lane >> 2);
            int cl = wn * 32 + ni * 8 + (lane & 3) * 2;
            #pragma unroll
            for (int half = 0; half < 2; ++half)
                *reinterpret_cast<float2*>(dst + (rl + half * 8) * 128 + cl) =
                    make_float2(acc[mi][ni][half * 2 + 0], acc[mi][ni][half * 2 + 1]);
        }
}

// ---------------------------------------------------------------------------
// Merged split: fp32 -> bf16 hi/lo for all 4 tensors in one launch.
// ---------------------------------------------------------------------------
__global__ __launch_bounds__(256)
void split_all_kernel(const float4* __restrict__ x,  const float4* __restrict__ wq,
                      const float4* __restrict__ wk, const float4* __restrict__ wv,
                      __nv_bfloat162* __restrict__ xh,  __nv_bfloat162* __restrict__ xl,
                      __nv_bfloat162* __restrict__ wqh, __nv_bfloat162* __restrict__ wql,
                      __nv_bfloat162* __restrict__ wkh, __nv_bfloat162* __restrict__ wkl,
                      __nv_bfloat162* __restrict__ wvh, __nv_bfloat162* __restrict__ wvl)
{
    const int t = blockIdx.y;
    const float4* in; __nv_bfloat162 *hi, *lo; int n4;
    if (t == 0)      { in = x;  hi = xh;  lo = xl;  n4 = M_*D_/4; }
    else if (t == 1) { in = wq; hi = wqh; lo = wql; n4 = D_*D_/4; }
    else if (t == 2) { in = wk; hi = wkh; lo = wkl; n4 = D_*D_/4; }
    else             { in = wv; hi = wvh; lo = wvl; n4 = D_*D_/4; }

    int i = blockIdx.x * 256 + threadIdx.x;
    if (i >= n4) return;
    float4 v = in[i];
    bf16 h0 = __float2bfloat16(v.x); bf16 l0 = __float2bfloat16(v.x - __bfloat162float(h0));
    bf16 h1 = __float2bfloat16(v.y); bf16 l1 = __float2bfloat16(v.y - __bfloat162float(h1));
    bf16 h2 = __float2bfloat16(v.z); bf16 l2 = __float2bfloat16(v.z - __bfloat162float(h2));
    bf16 h3 = __float2bfloat16(v.w); bf16 l3 = __float2bfloat16(v.w - __bfloat162float(h3));
    hi[2*i]   = __halves2bfloat162(h0, h1);
    hi[2*i+1] = __halves2bfloat162(h2, h3);
    lo[2*i]   = __halves2bfloat162(l0, l1);
    lo[2*i+1] = __halves2bfloat162(l2, l3);
}

// ---------------------------------------------------------------------------
// Q+K projection. Grid 1136: id<912 full tile (Q tiles 0..511, K tiles 0..399);
// id>=912: 224 k-half pieces of K tiles 400..511 -> fp32 partials in g_ph.
// ---------------------------------------------------------------------------
__global__ __launch_bounds__(NTHR, 2)
void tc_projqk_kernel(const bf16* __restrict__ Ah, const bf16* __restrict__ Al)
{
    extern __shared__ char smem[];
    uint32_t sb = smem_u32(smem);
    const int id = blockIdx.x;

    int tile, niter, k0e, piece;
    if (id < 912) { tile = id; niter = 32; k0e = 0; piece = -1; }
    else { int p = id - 912; tile = 912 + (p >> 1); niter = 16; k0e = (p & 1) * 512; piece = p; }
    const int z = tile >> 9, by = (tile >> 3) & 63, bx = tile & 7;

    const bf16 *Bh = (z == 0) ? g_wqh : g_wkh;
    const bf16 *Bl = (z == 0) ? g_wql : g_wkl;

    float acc[4][4][4];
    gemm_run<0>(sb,
        Ah + (size_t)by * 128 * D_ + k0e, Al + (size_t)by * 128 * D_ + k0e, D_,
        Bh + (size_t)bx * 128 * D_ + k0e, Bl + (size_t)bx * 128 * D_ + k0e, D_,
        niter, acc);

    if (piece < 0) {
        epi_bf16_split(acc, by, bx, (z == 0) ? g_qh : g_kh, (z == 0) ? g_ql : g_kl);
    } else {
        epi_f32_tile(acc, reinterpret_cast<float*>(g_ph) + (size_t)piece * 16384);
    }
}

// Combine 224 K half-partials into K hi/lo (tiles 912..1023, all z=1).
__global__ __launch_bounds__(256)
void qk_combine_kernel()
{
    const int t = blockIdx.x;              // [0,112)
    const int tile = 912 + t;
    const int by = (tile >> 3) & 63, bx = tile & 7;
    const float* scr = reinterpret_cast<const float*>(g_ph);
    const float4* p0 = reinterpret_cast<const float4*>(scr + (size_t)(2*t)   * 16384);
    const float4* p1 = reinterpret_cast<const float4*>(scr + (size_t)(2*t+1) * 16384);
    const int tid = threadIdx.x;

    #pragma unroll
    for (int j = 0; j < 16; ++j) {
        int f4 = j * 256 + tid;            // [0,4096)
        int r  = f4 >> 5;
        int c4 = f4 & 31;
        float4 a = p0[f4], b = p1[f4];
        float v[4] = {a.x + b.x, a.y + b.y, a.z + b.z, a.w + b.w};
        size_t base = (size_t)(by * 128 + r) * D_ + bx * 128 + c4 * 4;
        #pragma unroll
        for (int e = 0; e < 4; e += 2) {
            bf16 h0 = __float2bfloat16(v[e]);   bf16 l0 = __float2bfloat16(v[e]   - __bfloat162float(h0));
            bf16 h1 = __float2bfloat16(v[e+1]); bf16 l1 = __float2bfloat16(v[e+1] - __bfloat162float(h1));
            *reinterpret_cast<__nv_bfloat162*>(g_kh + base + e) = __halves2bfloat162(h0, h1);
            *reinterpret_cast<__nv_bfloat162*>(g_kl + base + e) = __halves2bfloat162(l0, l1);
        }
    }
}

// ---------------------------------------------------------------------------
// Merged scores + V-projection. Grid 1200:
//   id <  544: scores tile (b = id/136, triangular idx = id%136) -> g_s
//   id <  912: V-proj full tile vt = id-544 (vt 0..367)          -> g_vh/g_vl
//   id < 1200: V-proj half piece p = id-912 of vt = 368+(p>>1)   -> g_ph scratch
// ---------------------------------------------------------------------------
__global__ __launch_bounds__(NTHR, 2)
void tc_sv_kernel()
{
    extern __shared__ char smem[];
    uint32_t sb = smem_u32(smem);
    const int id = blockIdx.x;

    if (id < 544) {
        const int b = id / 136;
        const int idx = id % 136;
        int by = (int)((sqrtf(8.f * idx + 1.f) - 1.f) * 0.5f);
        while ((by + 1) * (by + 2) / 2 <= idx) ++by;
        while (by * (by + 1) / 2 > idx) --by;
        const int bx = idx - by * (by + 1) / 2;

        size_t aoff = ((size_t)b * S_ + by * 128) * D_;
        size_t boff = ((size_t)b * S_ + bx * 128) * D_;
        float acc[4][4][4];
        gemm_run<0>(sb, g_qh + aoff, g_ql + aoff, D_,
                        g_kh + boff, g_kl + boff, D_, D_ / 32, acc);

        const int tid = threadIdx.x, lane = tid & 31, wid = tid >> 5;
        const int wm = wid & 1, wn = wid >> 1;
        const bool diag = (bx == by);
        const float alpha = 0.03125f;
        float* out = g_s + (size_t)b * S_ * S_;

        #pragma unroll
        for (int mi = 0; mi < 4; ++mi)
            #pragma unroll
            for (int ni = 0; ni < 4; ++ni) {
                int r0 = by * 128 + wm * 64 + mi * 16 + (lane >> 2);
                int c0 = bx * 128 + wn * 32 + ni * 8 + (lane & 3) * 2;
                #pragma unroll
                for (int half = 0; half < 2; ++half) {
                    int gr = r0 + half * 8;
                    float s0 = acc[mi][ni][half * 2 + 0] * alpha;
                    float s1 = acc[mi][ni][half * 2 + 1] * alpha;
                    if (diag) {
                        if (c0 > gr)     s0 = -CUDART_INF_F;
                        if (c0 + 1 > gr) s1 = -CUDART_INF_F;
                    }
                    *reinterpret_cast<float2*>(out + (size_t)gr * S_ + c0) = make_float2(s0, s1);
                }
            }
    } else {
        int vt, niter, k0e, piece;
        if (id < 912) { vt = id - 544; niter = 32; k0e = 0; piece = -1; }
        else { int p = id - 912; vt = 368 + (p >> 1); niter = 16; k0e = (p & 1) * 512; piece = p; }
        const int by = vt >> 3, bx = vt & 7;

        float acc[4][4][4];
        gemm_run<0>(sb,
            g_xh + (size_t)by * 128 * D_ + k0e, g_xl + (size_t)by * 128 * D_ + k0e, D_,
            g_wvh + (size_t)bx * 128 * D_ + k0e, g_wvl + (size_t)bx * 128 * D_ + k0e, D_,
            niter, acc);

        if (piece < 0) epi_bf16_split(acc, by, bx, g_vh, g_vl);
        else epi_f32_tile(acc, reinterpret_cast<float*>(g_ph) + (size_t)piece * 16384);
    }
}

// Combine 288 V half-partials into V hi/lo (v-tiles 368..511).
__global__ __launch_bounds__(256)
void v_combine_kernel()
{
    const int t = blockIdx.x;              // [0,144)
    const int vt = 368 + t;
    const int by = vt >> 3, bx = vt & 7;
    const float* scr = reinterpret_cast<const float*>(g_ph);
    const float4* p0 = reinterpret_cast<const float4*>(scr + (size_t)(2*t)   * 16384);
    const float4* p1 = reinterpret_cast<const float4*>(scr + (size_t)(2*t+1) * 16384);
    const int tid = threadIdx.x;

    #pragma unroll
    for (int j = 0; j < 16; ++j) {
        int f4 = j * 256 + tid;
        int r  = f4 >> 5;
        int c4 = f4 & 31;
        float4 a = p0[f4], b = p1[f4];
        float v[4] = {a.x + b.x, a.y + b.y, a.z + b.z, a.w + b.w};
        size_t base = (size_t)(by * 128 + r) * D_ + bx * 128 + c4 * 4;
        #pragma unroll
        for (int e = 0; e < 4; e += 2) {
            bf16 h0 = __float2bfloat16(v[e]);   bf16 l0 = __float2bfloat16(v[e]   - __bfloat162float(h0));
            bf16 h1 = __float2bfloat16(v[e+1]); bf16 l1 = __float2bfloat16(v[e+1] - __bfloat162float(h1));
            *reinterpret_cast<__nv_bfloat162*>(g_vh + base + e) = __halves2bfloat162(h0, h1);
            *reinterpret_cast<__nv_bfloat162*>(g_vl + base + e) = __halves2bfloat162(l0, l1);
        }
    }
}

// ---------------------------------------------------------------------------
// Softmax over causal prefix; float2 in, bf16x2 h/l out.
// ---------------------------------------------------------------------------
__global__ __launch_bounds__(256)
void softmax_split_kernel()
{
    const int q = blockIdx.x;
    const int b = blockIdx.y;
    const size_t off = (size_t)b * S_ * S_ + (size_t)q * S_;
    const float2* row2 = reinterpret_cast<const float2*>(g_s + off);
    const int L2 = (((q >> 7) + 1) << 7) >> 1;
    const int tid = threadIdx.x;

    float2 v[4];
    float m = -CUDART_INF_F;
    #pragma unroll
    for (int j = 0; j < 4; ++j) {
        int i = tid + j * 256;
        if (i < L2) { v[j] = row2[i]; m = fmaxf(m, fmaxf(v[j].x, v[j].y)); }
        else        { v[j] = make_float2(-CUDART_INF_F, -CUDART_INF_F); }
    }
    #pragma unroll
    for (int o = 16; o > 0; o >>= 1) m = fmaxf(m, __shfl_xor_sync(0xFFFFFFFFu, m, o));
    __shared__ float red[8];
    if ((tid & 31) == 0) red[tid >> 5] = m;
    __syncthreads();
    float mg = red[0];
    #pragma unroll
    for (int j = 1; j < 8; ++j) mg = fmaxf(mg, red[j]);
    __syncthreads();

    float sum = 0.f;
    #pragma unroll
    for (int j = 0; j < 4; ++j) {
        int i = tid + j * 256;
        if (i < L2) {
            v[j].x = __expf(v[j].x - mg);
            v[j].y = __expf(v[j].y - mg);
            sum += v[j].x + v[j].y;
        }
    }
    #pragma unroll
    for (int o = 16; o > 0; o >>= 1) sum += __shfl_xor_sync(0xFFFFFFFFu, sum, o);
    if ((tid & 31) == 0) red[tid >> 5] = sum;
    __syncthreads();
    float tot = 0.f;
    #pragma unroll
    for (int j = 0; j < 8; ++j) tot += red[j];
    float inv = 1.0f / tot;

    __nv_bfloat162* ph2 = reinterpret_cast<__nv_bfloat162*>(g_ph + off);
    __nv_bfloat162* pl2 = reinterpret_cast<__nv_bfloat162*>(g_pl + off);
    #pragma unroll
    for (int j = 0; j < 4; ++j) {
        int i = tid + j * 256;
        if (i < L2) {
            float p0 = v[j].x * inv, p1 = v[j].y * inv;
            bf16 h0 = __float2bfloat16(p0); bf16 l0 = __float2bfloat16(p0 - __bfloat162float(h0));
            bf16 h1 = __float2bfloat16(p1); bf16 l1 = __float2bfloat16(p1 - __bfloat162float(h1));
            ph2[i] = __halves2bfloat162(h0, h1);
            pl2[i] = __halves2bfloat162(l0, l1);
        }
    }
}

// ---------------------------------------------------------------------------
// PV (all batches) with split-K; grid (8 bx, B, 24 order).
// ---------------------------------------------------------------------------
__global__ __launch_bounds__(NTHR, 2)
void tc_pv_kernel(float* __restrict__ out)
{
    const int bx = blockIdx.x;
    const int b  = blockIdx.y;
    const int o  = blockIdx.z;
    const int by = d_pv_by[o];
    const int piece = d_pv_piece[o];

    extern __shared__ char smem[];
    uint32_t sb = smem_u32(smem);

    const int total = (by + 1) * 4;
    int niter, k0i;
    if (piece < 0) { niter = total;      k0i = 0; }
    else           { niter = total >> 1; k0i = piece ? niter : 0; }
    const int k0 = k0i * 32;

    size_t aoff = (size_t)b * S_ * S_ + (size_t)by * 128 * S_ + k0;
    size_t boff = (size_t)b * S_ * D_ + (size_t)bx * 128 + (size_t)k0 * D_;

    float acc[4][4][4];
    gemm_run<1>(sb, g_ph + aoff, g_pl + aoff, S_,
                    g_vh + boff, g_vl + boff, D_, niter, acc);

    const int tid = threadIdx.x, lane = tid & 31, wid = tid >> 5;
    const int wm = wid & 1, wn = wid >> 1;

    if (piece == 0) {
        const int sidx = (by - 8) + 8 * (bx + 8 * b);
        epi_f32_tile(acc, g_s + (size_t)sidx * 16384);
    } else {
        #pragma unroll
        for (int mi = 0; mi < 4; ++mi)
            #pragma unroll
            for (int ni = 0; ni < 4; ++ni) {
                int r0 = by * 128 + wm * 64 + mi * 16 + (lane >> 2);
                int c0 = bx * 128 + wn * 32 + ni * 8 + (lane & 3) * 2;
                #pragma unroll
                for (int half = 0; half < 2; ++half) {
                    int gq = r0 + half * 8;
                    *reinterpret_cast<float2*>(out + ((size_t)(b * S_ + gq)) * D_ + c0) =
                        make_float2(acc[mi][ni][half * 2 + 0], acc[mi][ni][half * 2 + 1]);
                }
            }
    }
}

// Add the 256 lower-half partials into out. Deterministic (plain adds).
__global__ __launch_bounds__(256)
void pv_combine_kernel(float* __restrict__ out)
{
    const int tile = blockIdx.x;            // == sidx
    const int b  = tile >> 6;
    const int bx = (tile >> 3) & 7;
    const int by = (tile & 7) + 8;
    const float4* src = reinterpret_cast<const float4*>(g_s + (size_t)tile * 16384);
    const int tid = threadIdx.x;

    #pragma unroll
    for (int j = 0; j < 16; ++j) {
        int f4 = j * 256 + tid;
        int r  = f4 >> 5;
        int c4 = f4 & 31;
        float4 s = src[f4];
        float4* op = reinterpret_cast<float4*>(
            out + ((size_t)(b * S_ + by * 128 + r)) * D_ + bx * 128 + c4 * 4);
        float4 v = *op;
        v.x += s.x; v.y += s.y; v.z += s.z; v.w += s.w;
        *op = v;
    }
}

// ---------------------------------------------------------------------------
extern "C" void kernel_launch(void* const* d_in, const int* in_sizes, int n_in,
                              void* d_out, int out_size)
{
    const float* x  = (const float*)d_in[0];
    const float* wq = (const float*)d_in[1];
    const float* wk = (const float*)d_in[2];
    const float* wv = (const float*)d_in[3];
    float* out = (float*)d_out;

    bf16 *xh, *xl, *wqh, *wql, *wkh, *wkl, *wvh, *wvl;
    cudaGetSymbolAddress((void**)&xh,  g_xh);  cudaGetSymbolAddress((void**)&xl,  g_xl);
    cudaGetSymbolAddress((void**)&wqh, g_wqh); cudaGetSymbolAddress((void**)&wql, g_wql);
    cudaGetSymbolAddress((void**)&wkh, g_wkh); cudaGetSymbolAddress((void**)&wkl, g_wkl);
    cudaGetSymbolAddress((void**)&wvh, g_wvh); cudaGetSymbolAddress((void**)&wvl, g_wvl);

    static bool attr_done = false;
    if (!attr_done) {
        cudaFuncSetAttribute(tc_projqk_kernel, cudaFuncAttributeMaxDynamicSharedMemorySize, SMEM_TOTAL);
        cudaFuncSetAttribute(tc_sv_kernel,     cudaFuncAttributeMaxDynamicSharedMemorySize, SMEM_TOTAL);
        cudaFuncSetAttribute(tc_pv_kernel,     cudaFuncAttributeMaxDynamicSharedMemorySize, SMEM_TOTAL);
        attr_done = true;
    }

    // Splits (one launch)
    {
        dim3 gs((M_ * D_ / 4 + 255) / 256, 4);
        split_all_kernel<<<gs, 256>>>((const float4*)x, (const float4*)wq,
            (const float4*)wk, (const float4*)wv,
            (__nv_bfloat162*)xh, (__nv_bfloat162*)xl,
            (__nv_bfloat162*)wqh, (__nv_bfloat162*)wql,
            (__nv_bfloat162*)wkh, (__nv_bfloat162*)wkl,
            (__nv_bfloat162*)wvh, (__nv_bfloat162*)wvl);
    }

    // Q+K projections: 912 fulls (3 exact waves) + 224 tail halves
    tc_projqk_kernel<<<1136, NTHR, SMEM_TOTAL>>>(xh, xl);
    qk_combine_kernel<<<112, 256>>>();

    // Merged scores + V projection: 912 fulls (3 exact waves) + 288 halves
    tc_sv_kernel<<<1200, NTHR, SMEM_TOTAL>>>();
    v_combine_kernel<<<144, 256>>>();

    // Softmax + P split
    dim3 gsm(S_, B_);
    softmax_split_kernel<<<gsm, 256>>>();

    // P @ V with split-K (descending work order), then combine partials
    dim3 gpv(D_ / 128, B_, 24);
    tc_pv_kernel<<<gpv, NTHR, SMEM_TOTAL>>>(out);
    pv_combine_kernel<<<256, 256>>>(out);
}